// round 7
// baseline (speedup 1.0000x reference)
#include <cuda_runtime.h>
#include <math.h>
#include <stdint.h>

#define B_ 4
#define S_ 2048
#define D_ 1024
#define F_ 4096

// ---------------- scratch (device globals: allocation-free) ----------------
__device__ float g_scores[(size_t)B_ * S_ * S_];   //  64 MB (scores -> probs, tf32-rounded)
__device__ float g_attn  [(size_t)B_ * S_ * D_];   //  32 MB
__device__ float g_x     [(size_t)B_ * S_ * D_];   //  32 MB (exact LN1 out)
__device__ float g_xr    [(size_t)B_ * S_ * D_];   //  32 MB (tf32-rounded LN1 out)
__device__ float g_y     [(size_t)B_ * S_ * F_];   // 128 MB (tf32-rounded gelu out)
__device__ float g_f     [(size_t)B_ * S_ * D_];   //  32 MB
__device__ float g_hr    [(size_t)B_ * S_ * D_];   //  32 MB (tf32-rounded h)
__device__ float g_w1r   [(size_t)D_ * F_];        //  16 MB
__device__ float g_w2r   [(size_t)F_ * D_];        //  16 MB

// ---------------- helpers ----------------
__device__ __forceinline__ float tf32r(float x) {
    uint32_t u;
    asm("cvt.rna.tf32.f32 %0, %1;" : "=r"(u) : "f"(x));
    return __uint_as_float(u);
}
__device__ __forceinline__ float gelu_exact(float x) {
    return 0.5f * x * (1.0f + erff(x * 0.7071067811865476f));
}
__device__ __forceinline__ float warpSum(float v) {
#pragma unroll
    for (int o = 16; o; o >>= 1) v += __shfl_xor_sync(0xffffffffu, v, o);
    return v;
}
__device__ __forceinline__ float warpMax(float v) {
#pragma unroll
    for (int o = 16; o; o >>= 1) v = fmaxf(v, __shfl_xor_sync(0xffffffffu, v, o));
    return v;
}
__device__ __forceinline__ void mma8(float* c, const uint32_t* a, uint32_t b0, uint32_t b1) {
    asm volatile(
        "mma.sync.aligned.m16n8k8.row.col.f32.tf32.tf32.f32 "
        "{%0,%1,%2,%3}, {%4,%5,%6,%7}, {%8,%9}, {%0,%1,%2,%3};"
        : "+f"(c[0]), "+f"(c[1]), "+f"(c[2]), "+f"(c[3])
        : "r"(a[0]), "r"(a[1]), "r"(a[2]), "r"(a[3]), "r"(b0), "r"(b1));
}
__device__ __forceinline__ void cpasync16(float* smem, const float* gmem) {
    uint32_t s = (uint32_t)__cvta_generic_to_shared(smem);
    asm volatile("cp.async.cg.shared.global [%0], [%1], 16;" :: "r"(s), "l"(gmem));
}
__device__ __forceinline__ void cp_commit() {
    asm volatile("cp.async.commit_group;");
}
template <int N>
__device__ __forceinline__ void cp_wait() {
    asm volatile("cp.async.wait_group %0;" :: "n"(N));
}

// ---------------- tf32 rounding pass ----------------
__global__ void round_kernel(const float* __restrict__ src, float* __restrict__ dst, int n4) {
    int i = blockIdx.x * blockDim.x + threadIdx.x;
    if (i < n4) {
        float4 v = ((const float4*)src)[i];
        v.x = tf32r(v.x); v.y = tf32r(v.y); v.z = tf32r(v.z); v.w = tf32r(v.w);
        ((float4*)dst)[i] = v;
    }
}

// ---------------- TF32 tensor-core GEMM with cp.async 3-stage pipeline ------
// A: [M,K] row-major (tf32-pre-rounded). B: BT ? [N,K] : [K,N] (tf32-pre-rounded).
// Block 128x128x32, 256 threads, 8 warps (2x4) of 64x32 tiles, mma.m16n8k8.
// Smem stages: A[128][36], B: BT -> [128][36], NN -> [32][136]  (both fit 4608 floats)
// EPI: 0 -> C = acc*alpha ; 1 -> C = tf32r(gelu(acc + bias)) ; 2 -> C = acc + bias
#define ASTRIDE 36
#define BSTRIDE_NN 136
#define STAGE_F 4608          // floats per stage per matrix (18432 B)
#define SMEM_BYTES (3 * 2 * STAGE_F * 4)

template <bool BT, int EPI>
__global__ void __launch_bounds__(256, 2)
mma_gemm(const float* __restrict__ A, const float* __restrict__ B,
         float* __restrict__ C, int M, int N, int K,
         size_t sA, size_t sB, size_t sC,
         const float* __restrict__ bias, float alpha) {
    extern __shared__ float sm[];

    A += (size_t)blockIdx.z * sA;
    B += (size_t)blockIdx.z * sB;
    C += (size_t)blockIdx.z * sC;

    const int tid  = threadIdx.x;
    const int lane = tid & 31, warp = tid >> 5;
    const int wm = warp >> 2, wn = warp & 3;     // 2 x 4 warp grid
    const int g = lane >> 2, tig = lane & 3;

    // ---- cp.async mappings ----
    const int arow = tid >> 1;                // 0..127
    const int acol = (tid & 1) * 16;          // 0 or 16 (each thread: 4x16B = 64B)
    const float* Ag = A + (size_t)(blockIdx.y * 128 + arow) * K + acol;

    const float* Bg;
    int brow, bcol;
    if (BT) {
        brow = tid >> 1; bcol = (tid & 1) * 16;
        Bg = B + (size_t)(blockIdx.x * 128 + brow) * K + bcol;
    } else {
        brow = tid >> 3;                      // 0..31 (k)
        bcol = (tid & 7) * 16;                // 0..112 (n)
        Bg = B + (size_t)brow * N + blockIdx.x * 128 + bcol;
    }

    const int nch = K >> 5;

    // issue one stage's loads
    auto issue = [&](int st, int ch) {
        float* As = sm + st * STAGE_F;
        float* Bs = sm + (3 + st) * STAGE_F;
        const float* ag = Ag + ch * 32;
#pragma unroll
        for (int j = 0; j < 4; j++)
            cpasync16(As + arow * ASTRIDE + acol + 4 * j, ag + 4 * j);
        if (BT) {
            const float* bg = Bg + ch * 32;
#pragma unroll
            for (int j = 0; j < 4; j++)
                cpasync16(Bs + brow * ASTRIDE + bcol + 4 * j, bg + 4 * j);
        } else {
            const float* bg = Bg + (size_t)ch * 32 * N;
#pragma unroll
            for (int j = 0; j < 4; j++)
                cpasync16(Bs + brow * BSTRIDE_NN + bcol + 4 * j, bg + 4 * j);
        }
    };

    // prologue: stages 0,1
    issue(0, 0); cp_commit();
    issue(1, 1); cp_commit();

    float acc[4][4][4];
#pragma unroll
    for (int i = 0; i < 4; i++)
#pragma unroll
        for (int j = 0; j < 4; j++)
#pragma unroll
            for (int p = 0; p < 4; p++) acc[i][j][p] = 0.f;

    int st = 0;
    for (int ch = 0; ch < nch; ch++) {
        cp_wait<1>();            // stage for chunk ch has landed
        __syncthreads();         // also protects buffer st from next issue

        if (ch + 2 < nch) issue((st + 2) % 3, ch + 2);
        cp_commit();             // commit (possibly empty) to keep counts aligned

        const uint32_t* Asu = (const uint32_t*)(sm + st * STAGE_F);
        const uint32_t* Bsu = (const uint32_t*)(sm + (3 + st) * STAGE_F);

#pragma unroll
        for (int ks = 0; ks < 4; ks++) {
            uint32_t a[4][4];
#pragma unroll
            for (int mt = 0; mt < 4; mt++) {
                const int r = wm * 64 + mt * 16 + g;
                const int c = ks * 8 + tig;
                a[mt][0] = Asu[r * ASTRIDE + c];
                a[mt][1] = Asu[(r + 8) * ASTRIDE + c];
                a[mt][2] = Asu[r * ASTRIDE + c + 4];
                a[mt][3] = Asu[(r + 8) * ASTRIDE + c + 4];
            }
#pragma unroll
            for (int nt = 0; nt < 4; nt++) {
                const int n = wn * 32 + nt * 8 + g;
                uint32_t b0, b1;
                if (BT) {
                    b0 = Bsu[n * ASTRIDE + ks * 8 + tig];
                    b1 = Bsu[n * ASTRIDE + ks * 8 + tig + 4];
                } else {
                    b0 = Bsu[(ks * 8 + tig) * BSTRIDE_NN + n];
                    b1 = Bsu[(ks * 8 + tig + 4) * BSTRIDE_NN + n];
                }
#pragma unroll
                for (int mt = 0; mt < 4; mt++) mma8(acc[mt][nt], a[mt], b0, b1);
            }
        }
        st = (st + 1) % 3;
    }

    // ---- epilogue ----
#pragma unroll
    for (int mt = 0; mt < 4; mt++) {
        const int r0 = blockIdx.y * 128 + wm * 64 + mt * 16 + g;
#pragma unroll
        for (int nt = 0; nt < 4; nt++) {
            const int c0 = blockIdx.x * 128 + wn * 32 + nt * 8 + 2 * tig;
            float v0 = acc[mt][nt][0], v1 = acc[mt][nt][1];
            float v2 = acc[mt][nt][2], v3 = acc[mt][nt][3];
            if (EPI == 0) {
                v0 *= alpha; v1 *= alpha; v2 *= alpha; v3 *= alpha;
            } else {
                const float bb0 = bias[c0], bb1 = bias[c0 + 1];
                v0 += bb0; v1 += bb1; v2 += bb0; v3 += bb1;
                if (EPI == 1) {
                    v0 = tf32r(gelu_exact(v0)); v1 = tf32r(gelu_exact(v1));
                    v2 = tf32r(gelu_exact(v2)); v3 = tf32r(gelu_exact(v3));
                }
            }
            *(float2*)(C + (size_t)r0 * N + c0)       = make_float2(v0, v1);
            *(float2*)(C + (size_t)(r0 + 8) * N + c0) = make_float2(v2, v3);
        }
    }
}

// ---------------- softmax over rows of [B*S, S] with additive mask[b, k] ----
__global__ void softmax_kernel(float* __restrict__ P, const float* __restrict__ mask) {
    __shared__ float sh[8];
    const int row = blockIdx.x;
    const int b   = row >> 11;
    float* p = P + (size_t)row * S_;
    const float* m = mask + (size_t)b * S_;
    const int tid = threadIdx.x;

    float v[8];
    float mx = -1e30f;
#pragma unroll
    for (int i = 0; i < 8; i++) {
        const int idx = tid + (i << 8);
        v[i] = p[idx] + m[idx];
        mx = fmaxf(mx, v[i]);
    }
    mx = warpMax(mx);
    if ((tid & 31) == 0) sh[tid >> 5] = mx;
    __syncthreads();
    mx = sh[0];
#pragma unroll
    for (int j = 1; j < 8; j++) mx = fmaxf(mx, sh[j]);

    float s = 0.f;
#pragma unroll
    for (int i = 0; i < 8; i++) { v[i] = expf(v[i] - mx); s += v[i]; }
    s = warpSum(s);
    __syncthreads();
    if ((tid & 31) == 0) sh[tid >> 5] = s;
    __syncthreads();
    s = 0.f;
#pragma unroll
    for (int j = 0; j < 8; j++) s += sh[j];
    const float inv = 1.0f / s;
#pragma unroll
    for (int i = 0; i < 8; i++) p[tid + (i << 8)] = tf32r(v[i] * inv);
}

// ---------------- out = LayerNorm(X + Y); optionally also tf32-rounded copy ----
template <bool WR>
__global__ void add_ln_kernel(const float* __restrict__ X, const float* __restrict__ Y,
                              const float* __restrict__ gamma, const float* __restrict__ beta,
                              float* __restrict__ O, float* __restrict__ OR_) {
    __shared__ float shs[8], shq[8];
    const int row = blockIdx.x;
    const int tid = threadIdx.x;
    const size_t base = (size_t)row * D_ + tid * 4;

    const float4 a = *(const float4*)(X + base);
    const float4 b = *(const float4*)(Y + base);
    const float v0 = a.x + b.x, v1 = a.y + b.y, v2 = a.z + b.z, v3 = a.w + b.w;

    float s = v0 + v1 + v2 + v3;
    float q = v0 * v0 + v1 * v1 + v2 * v2 + v3 * v3;
    s = warpSum(s); q = warpSum(q);
    if ((tid & 31) == 0) { shs[tid >> 5] = s; shq[tid >> 5] = q; }
    __syncthreads();
    s = 0.f; q = 0.f;
#pragma unroll
    for (int j = 0; j < 8; j++) { s += shs[j]; q += shq[j]; }
    const float mean = s * (1.0f / D_);
    const float var  = q * (1.0f / D_) - mean * mean;
    const float rstd = rsqrtf(var + 1e-5f);

    const float4 gm = *(const float4*)(gamma + tid * 4);
    const float4 bt = *(const float4*)(beta  + tid * 4);
    float4 o;
    o.x = (v0 - mean) * rstd * gm.x + bt.x;
    o.y = (v1 - mean) * rstd * gm.y + bt.y;
    o.z = (v2 - mean) * rstd * gm.z + bt.z;
    o.w = (v3 - mean) * rstd * gm.w + bt.w;
    *(float4*)(O + base) = o;
    if (WR) {
        float4 r;
        r.x = tf32r(o.x); r.y = tf32r(o.y); r.z = tf32r(o.z); r.w = tf32r(o.w);
        *(float4*)(OR_ + base) = r;
    }
}

// ---------------- launch ----------------
extern "C" void kernel_launch(void* const* d_in, const int* in_sizes, int n_in,
                              void* d_out, int out_size) {
    const float* h   = (const float*)d_in[0];
    const float* msk = (const float*)d_in[1];
    const float* w1  = (const float*)d_in[2];
    const float* b1  = (const float*)d_in[3];
    const float* w2  = (const float*)d_in[4];
    const float* b2  = (const float*)d_in[5];
    const float* g1  = (const float*)d_in[6];
    const float* be1 = (const float*)d_in[7];
    const float* g2  = (const float*)d_in[8];
    const float* be2 = (const float*)d_in[9];
    float* out = (float*)d_out;

    float *scores, *attn, *x, *xr, *y, *f, *hr, *w1r, *w2r;
    cudaGetSymbolAddress((void**)&scores, g_scores);
    cudaGetSymbolAddress((void**)&attn,   g_attn);
    cudaGetSymbolAddress((void**)&x,      g_x);
    cudaGetSymbolAddress((void**)&xr,     g_xr);
    cudaGetSymbolAddress((void**)&y,      g_y);
    cudaGetSymbolAddress((void**)&f,      g_f);
    cudaGetSymbolAddress((void**)&hr,     g_hr);
    cudaGetSymbolAddress((void**)&w1r,    g_w1r);
    cudaGetSymbolAddress((void**)&w2r,    g_w2r);

    // opt-in to large dynamic smem (idempotent, host-side)
    cudaFuncSetAttribute(mma_gemm<true, 0>,  cudaFuncAttributeMaxDynamicSharedMemorySize, SMEM_BYTES);
    cudaFuncSetAttribute(mma_gemm<false, 0>, cudaFuncAttributeMaxDynamicSharedMemorySize, SMEM_BYTES);
    cudaFuncSetAttribute(mma_gemm<false, 1>, cudaFuncAttributeMaxDynamicSharedMemorySize, SMEM_BYTES);
    cudaFuncSetAttribute(mma_gemm<false, 2>, cudaFuncAttributeMaxDynamicSharedMemorySize, SMEM_BYTES);

    // 0) tf32-round constants/inputs
    round_kernel<<<(B_ * S_ * D_ / 4 + 255) / 256, 256>>>(h,  hr,  B_ * S_ * D_ / 4);
    round_kernel<<<(D_ * F_ / 4 + 255) / 256, 256>>>(w1, w1r, D_ * F_ / 4);
    round_kernel<<<(F_ * D_ / 4 + 255) / 256, 256>>>(w2, w2r, F_ * D_ / 4);

    // 1) scores = (h @ h^T) / sqrt(D)
    mma_gemm<true, 0><<<dim3(S_ / 128, S_ / 128, B_), 256, SMEM_BYTES>>>(
        hr, hr, scores, S_, S_, D_,
        (size_t)S_ * D_, (size_t)S_ * D_, (size_t)S_ * S_, nullptr, 0.03125f);

    // 2) probs = tf32r(softmax(scores + mask))  (in place)
    softmax_kernel<<<B_ * S_, 256>>>(scores, msk);

    // 3) attn = probs @ h
    mma_gemm<false, 0><<<dim3(D_ / 128, S_ / 128, B_), 256, SMEM_BYTES>>>(
        scores, hr, attn, S_, D_, S_,
        (size_t)S_ * S_, (size_t)S_ * D_, (size_t)S_ * D_, nullptr, 1.0f);

    // 4) x = LN1(h + attn)  (+ tf32 copy)
    add_ln_kernel<true><<<B_ * S_, 256>>>(h, attn, g1, be1, x, xr);

    // 5) y = tf32r(gelu(x @ w1 + b1))
    mma_gemm<false, 1><<<dim3(F_ / 128, (B_ * S_) / 128, 1), 256, SMEM_BYTES>>>(
        xr, w1r, y, B_ * S_, F_, D_, 0, 0, 0, b1, 1.0f);

    // 6) f = y @ w2 + b2
    mma_gemm<false, 2><<<dim3(D_ / 128, (B_ * S_) / 128, 1), 256, SMEM_BYTES>>>(
        y, w2r, f, B_ * S_, D_, F_, 0, 0, 0, b2, 1.0f);

    // 7) out = LN2(x + f)
    add_ln_kernel<false><<<B_ * S_, 256>>>(x, f, g2, be2, out, nullptr);
}

// round 9
// speedup vs baseline: 1.2478x; 1.2478x over previous
#include <cuda_runtime.h>
#include <math.h>
#include <stdint.h>

#define B_ 4
#define S_ 2048
#define D_ 1024
#define F_ 4096

// ---------------- scratch (device globals: allocation-free) ----------------
__device__ float g_scores[(size_t)B_ * S_ * S_];   //  64 MB (scores -> probs, tf32-rounded)
__device__ float g_attn  [(size_t)B_ * S_ * D_];   //  32 MB
__device__ float g_x     [(size_t)B_ * S_ * D_];   //  32 MB (exact LN1 out)
__device__ float g_xr    [(size_t)B_ * S_ * D_];   //  32 MB (tf32-rounded LN1 out)
__device__ float g_y     [(size_t)B_ * S_ * F_];   // 128 MB (tf32-rounded gelu out)
__device__ float g_f     [(size_t)B_ * S_ * D_];   //  32 MB
__device__ float g_hr    [(size_t)B_ * S_ * D_];   //  32 MB (tf32-rounded h, [B,S,D])
__device__ float g_hrT   [(size_t)B_ * D_ * S_];   //  32 MB (tf32-rounded h^T, [B,D,S])
__device__ float g_w1t   [(size_t)F_ * D_];        //  16 MB (tf32-rounded w1^T, [F,D])
__device__ float g_w2t   [(size_t)D_ * F_];        //  16 MB (tf32-rounded w2^T, [D,F])

// ---------------- helpers ----------------
__device__ __forceinline__ float tf32r(float x) {
    uint32_t u;
    asm("cvt.rna.tf32.f32 %0, %1;" : "=r"(u) : "f"(x));
    return __uint_as_float(u);
}
__device__ __forceinline__ float gelu_exact(float x) {
    return 0.5f * x * (1.0f + erff(x * 0.7071067811865476f));
}
__device__ __forceinline__ float warpSum(float v) {
#pragma unroll
    for (int o = 16; o; o >>= 1) v += __shfl_xor_sync(0xffffffffu, v, o);
    return v;
}
__device__ __forceinline__ float warpMax(float v) {
#pragma unroll
    for (int o = 16; o; o >>= 1) v = fmaxf(v, __shfl_xor_sync(0xffffffffu, v, o));
    return v;
}
__device__ __forceinline__ void mma8(float* c, const uint32_t* a, uint32_t b0, uint32_t b1) {
    asm volatile(
        "mma.sync.aligned.m16n8k8.row.col.f32.tf32.tf32.f32 "
        "{%0,%1,%2,%3}, {%4,%5,%6,%7}, {%8,%9}, {%0,%1,%2,%3};"
        : "+f"(c[0]), "+f"(c[1]), "+f"(c[2]), "+f"(c[3])
        : "r"(a[0]), "r"(a[1]), "r"(a[2]), "r"(a[3]), "r"(b0), "r"(b1));
}
__device__ __forceinline__ void ldsm4(uint32_t& r0, uint32_t& r1, uint32_t& r2, uint32_t& r3,
                                      uint32_t addr) {
    asm volatile("ldmatrix.sync.aligned.m8n8.x4.shared.b16 {%0,%1,%2,%3}, [%4];"
                 : "=r"(r0), "=r"(r1), "=r"(r2), "=r"(r3) : "r"(addr));
}
__device__ __forceinline__ void cpasync16(uint32_t s, const float* g) {
    asm volatile("cp.async.cg.shared.global [%0], [%1], 16;" :: "r"(s), "l"(g));
}
__device__ __forceinline__ void cp_commit() { asm volatile("cp.async.commit_group;"); }
template <int N>
__device__ __forceinline__ void cp_wait() {
    asm volatile("cp.async.wait_group %0;" :: "n"(N));
}

// ---------------- tf32 rounding pass ----------------
__global__ void round_kernel(const float* __restrict__ src, float* __restrict__ dst, int n4) {
    int i = blockIdx.x * blockDim.x + threadIdx.x;
    if (i < n4) {
        float4 v = ((const float4*)src)[i];
        v.x = tf32r(v.x); v.y = tf32r(v.y); v.z = tf32r(v.z); v.w = tf32r(v.w);
        ((float4*)dst)[i] = v;
    }
}

// ---------------- round + transpose: src[z][R][C] -> dst[z][C][R] ----------------
__global__ void roundT_kernel(const float* __restrict__ src, float* __restrict__ dst,
                              int R, int C) {
    __shared__ float t[32][33];
    src += (size_t)blockIdx.z * R * C;
    dst += (size_t)blockIdx.z * R * C;
    const int r0 = blockIdx.y * 32, c0 = blockIdx.x * 32;
    const int tx = threadIdx.x, ty = threadIdx.y;   // 32 x 8
#pragma unroll
    for (int i = 0; i < 32; i += 8)
        t[ty + i][tx] = tf32r(src[(size_t)(r0 + ty + i) * C + c0 + tx]);
    __syncthreads();
#pragma unroll
    for (int i = 0; i < 32; i += 8)
        dst[(size_t)(c0 + ty + i) * R + r0 + tx] = t[tx][ty + i];
}

// ---------------- TF32 mma.sync GEMM with ldmatrix + cp.async ----------------
// C[M,N] = epi( A[M,K] @ B[N,K]^T ), A,B tf32-pre-rounded, K-major, K%32==0.
// 128x128x32 block, 256 threads, 8 warps (2x4) of 64x32, mma.m16n8k8.
// Smem: 128B rows, XOR-swizzled 16B chunks (phys = j ^ (row&7)), 3 stages.
#define STAGE_B 16384                       // 128 rows x 128 B
#define SMEM_BYTES (3 * 2 * STAGE_B)        // 98304 B

template <int EPI>
__global__ void __launch_bounds__(256, 2)
mma_gemm(const float* __restrict__ A, const float* __restrict__ B,
         float* __restrict__ C, int M, int N, int K,
         size_t sA, size_t sB, size_t sC,
         const float* __restrict__ bias, float alpha) {
    extern __shared__ float sm[];
    const uint32_t sb = (uint32_t)__cvta_generic_to_shared(sm);

    A += (size_t)blockIdx.z * sA;
    B += (size_t)blockIdx.z * sB;
    C += (size_t)blockIdx.z * sC;

    const int tid  = threadIdx.x;
    const int lane = tid & 31, warp = tid >> 5;
    const int wm = warp >> 2, wn = warp & 3;     // 2 x 4 warp grid

    // ---- cp.async mapping: thread t -> row t>>1, 4 chunks of 16B ----
    const int arow = tid >> 1;
    const int ac4  = (tid & 1) * 4;              // first logical chunk (0 or 4)
    const float* Ag = A + (size_t)(blockIdx.y * 128 + arow) * K + (tid & 1) * 16;
    const float* Bg = B + (size_t)(blockIdx.x * 128 + arow) * K + (tid & 1) * 16;
    const uint32_t aRow = sb + (uint32_t)arow * 128;
    const uint32_t bRow = sb + 3 * STAGE_B + (uint32_t)arow * 128;
    const int rsw = arow & 7;

    auto issue = [&](int ch, int s) {
        const float* ag = Ag + ch * 32;
        const float* bg = Bg + ch * 32;
        const uint32_t as = aRow + s * STAGE_B;
        const uint32_t bs = bRow + s * STAGE_B;
#pragma unroll
        for (int j = 0; j < 4; j++) {
            const uint32_t off = (uint32_t)(((ac4 + j) ^ rsw) * 16);
            cpasync16(as + off, ag + j * 4);
            cpasync16(bs + off, bg + j * 4);
        }
    };

    // ---- ldmatrix per-lane address components ----
    const int lm = lane >> 3, ri = lane & 7;     // matrix idx, row-in-matrix
    // A: matrix m -> (row + (m&1)*8, kcol + (m>>1)*16B)   => regs a0,a1,a2,a3
    uint32_t aOff[4]; int aSel[4];
#pragma unroll
    for (int mt = 0; mt < 4; mt++) {
        const int r = wm * 64 + mt * 16 + (lm & 1) * 8 + ri;
        aOff[mt] = (uint32_t)r * 128;
        aSel[mt] = r & 7;
    }
    const int aCh = lm >> 1;                     // k-chunk offset (0/1) for this lane
    // B: matrix m -> (nrow + (m>>1)*8, kcol + (m&1)*16B)  => regs (b0,b1) x 2 n-tiles
    uint32_t bOff[2]; int bSel[2];
#pragma unroll
    for (int np = 0; np < 2; np++) {
        const int r = wn * 32 + np * 16 + (lm >> 1) * 8 + ri;
        bOff[np] = (uint32_t)r * 128;
        bSel[np] = r & 7;
    }
    const int bCh = lm & 1;

    const int nch = K >> 5;

    // prologue: chunks 0,1
    issue(0, 0); cp_commit();
    issue(1, 1); cp_commit();

    float acc[4][4][4];
#pragma unroll
    for (int i = 0; i < 4; i++)
#pragma unroll
        for (int j = 0; j < 4; j++)
#pragma unroll
            for (int p = 0; p < 4; p++) acc[i][j][p] = 0.f;

    for (int ch = 0; ch < nch; ch++) {
        const int s = ch % 3;
        cp_wait<1>();
        __syncthreads();

        if (ch + 2 < nch) issue(ch + 2, (ch + 2) % 3);
        cp_commit();

        const uint32_t aSt = sb + s * STAGE_B;
        const uint32_t bSt = sb + 3 * STAGE_B + s * STAGE_B;

#pragma unroll
        for (int ks = 0; ks < 4; ks++) {
            uint32_t a[4][4];
#pragma unroll
            for (int mt = 0; mt < 4; mt++)
                ldsm4(a[mt][0], a[mt][1], a[mt][2], a[mt][3],
                      aSt + aOff[mt] + (uint32_t)(((2 * ks + aCh) ^ aSel[mt]) << 4));
            uint32_t bb[2][4];
#pragma unroll
            for (int np = 0; np < 2; np++)
                ldsm4(bb[np][0], bb[np][1], bb[np][2], bb[np][3],
                      bSt + bOff[np] + (uint32_t)(((2 * ks + bCh) ^ bSel[np]) << 4));
#pragma unroll
            for (int nt = 0; nt < 4; nt++) {
                const uint32_t b0 = bb[nt >> 1][(nt & 1) * 2];
                const uint32_t b1 = bb[nt >> 1][(nt & 1) * 2 + 1];
#pragma unroll
                for (int mt = 0; mt < 4; mt++) mma8(acc[mt][nt], a[mt], b0, b1);
            }
        }
    }

    // ---- epilogue ----
    const int g = lane >> 2, tig = lane & 3;
#pragma unroll
    for (int mt = 0; mt < 4; mt++) {
        const int r0 = blockIdx.y * 128 + wm * 64 + mt * 16 + g;
#pragma unroll
        for (int nt = 0; nt < 4; nt++) {
            const int c0 = blockIdx.x * 128 + wn * 32 + nt * 8 + 2 * tig;
            float v0 = acc[mt][nt][0], v1 = acc[mt][nt][1];
            float v2 = acc[mt][nt][2], v3 = acc[mt][nt][3];
            if (EPI == 0) {
                v0 *= alpha; v1 *= alpha; v2 *= alpha; v3 *= alpha;
            } else {
                const float bb0 = bias[c0], bb1 = bias[c0 + 1];
                v0 += bb0; v1 += bb1; v2 += bb0; v3 += bb1;
                if (EPI == 1) {
                    v0 = tf32r(gelu_exact(v0)); v1 = tf32r(gelu_exact(v1));
                    v2 = tf32r(gelu_exact(v2)); v3 = tf32r(gelu_exact(v3));
                }
            }
            *(float2*)(C + (size_t)r0 * N + c0)       = make_float2(v0, v1);
            *(float2*)(C + (size_t)(r0 + 8) * N + c0) = make_float2(v2, v3);
        }
    }
}

// ---------------- softmax over rows of [B*S, S] with additive mask[b, k] ----
__global__ void softmax_kernel(float* __restrict__ P, const float* __restrict__ mask) {
    __shared__ float sh[8];
    const int row = blockIdx.x;
    const int b   = row >> 11;
    float* p = P + (size_t)row * S_;
    const float* m = mask + (size_t)b * S_;
    const int tid = threadIdx.x;

    float v[8];
    float mx = -1e30f;
#pragma unroll
    for (int i = 0; i < 8; i++) {
        const int idx = tid + (i << 8);
        v[i] = p[idx] + m[idx];
        mx = fmaxf(mx, v[i]);
    }
    mx = warpMax(mx);
    if ((tid & 31) == 0) sh[tid >> 5] = mx;
    __syncthreads();
    mx = sh[0];
#pragma unroll
    for (int j = 1; j < 8; j++) mx = fmaxf(mx, sh[j]);

    float s = 0.f;
#pragma unroll
    for (int i = 0; i < 8; i++) { v[i] = expf(v[i] - mx); s += v[i]; }
    s = warpSum(s);
    __syncthreads();
    if ((tid & 31) == 0) sh[tid >> 5] = s;
    __syncthreads();
    s = 0.f;
#pragma unroll
    for (int j = 0; j < 8; j++) s += sh[j];
    const float inv = 1.0f / s;
#pragma unroll
    for (int i = 0; i < 8; i++) p[tid + (i << 8)] = tf32r(v[i] * inv);
}

// ---------------- out = LayerNorm(X + Y); optionally also tf32-rounded copy ----
template <bool WR>
__global__ void add_ln_kernel(const float* __restrict__ X, const float* __restrict__ Y,
                              const float* __restrict__ gamma, const float* __restrict__ beta,
                              float* __restrict__ O, float* __restrict__ OR_) {
    __shared__ float shs[8], shq[8];
    const int row = blockIdx.x;
    const int tid = threadIdx.x;
    const size_t base = (size_t)row * D_ + tid * 4;

    const float4 a = *(const float4*)(X + base);
    const float4 b = *(const float4*)(Y + base);
    const float v0 = a.x + b.x, v1 = a.y + b.y, v2 = a.z + b.z, v3 = a.w + b.w;

    float s = v0 + v1 + v2 + v3;
    float q = v0 * v0 + v1 * v1 + v2 * v2 + v3 * v3;
    s = warpSum(s); q = warpSum(q);
    if ((tid & 31) == 0) { shs[tid >> 5] = s; shq[tid >> 5] = q; }
    __syncthreads();
    s = 0.f; q = 0.f;
#pragma unroll
    for (int j = 0; j < 8; j++) { s += shs[j]; q += shq[j]; }
    const float mean = s * (1.0f / D_);
    const float var  = q * (1.0f / D_) - mean * mean;
    const float rstd = rsqrtf(var + 1e-5f);

    const float4 gm = *(const float4*)(gamma + tid * 4);
    const float4 bt = *(const float4*)(beta  + tid * 4);
    float4 o;
    o.x = (v0 - mean) * rstd * gm.x + bt.x;
    o.y = (v1 - mean) * rstd * gm.y + bt.y;
    o.z = (v2 - mean) * rstd * gm.z + bt.z;
    o.w = (v3 - mean) * rstd * gm.w + bt.w;
    *(float4*)(O + base) = o;
    if (WR) {
        float4 rr;
        rr.x = tf32r(o.x); rr.y = tf32r(o.y); rr.z = tf32r(o.z); rr.w = tf32r(o.w);
        *(float4*)(OR_ + base) = rr;
    }
}

// ---------------- launch ----------------
extern "C" void kernel_launch(void* const* d_in, const int* in_sizes, int n_in,
                              void* d_out, int out_size) {
    const float* h   = (const float*)d_in[0];
    const float* msk = (const float*)d_in[1];
    const float* w1  = (const float*)d_in[2];
    const float* b1  = (const float*)d_in[3];
    const float* w2  = (const float*)d_in[4];
    const float* b2  = (const float*)d_in[5];
    const float* g1  = (const float*)d_in[6];
    const float* be1 = (const float*)d_in[7];
    const float* g2  = (const float*)d_in[8];
    const float* be2 = (const float*)d_in[9];
    float* out = (float*)d_out;

    float *scores, *attn, *x, *xr, *y, *f, *hr, *hrT, *w1t, *w2t;
    cudaGetSymbolAddress((void**)&scores, g_scores);
    cudaGetSymbolAddress((void**)&attn,   g_attn);
    cudaGetSymbolAddress((void**)&x,      g_x);
    cudaGetSymbolAddress((void**)&xr,     g_xr);
    cudaGetSymbolAddress((void**)&y,      g_y);
    cudaGetSymbolAddress((void**)&f,      g_f);
    cudaGetSymbolAddress((void**)&hr,     g_hr);
    cudaGetSymbolAddress((void**)&hrT,    g_hrT);
    cudaGetSymbolAddress((void**)&w1t,    g_w1t);
    cudaGetSymbolAddress((void**)&w2t,    g_w2t);

    cudaFuncSetAttribute(mma_gemm<0>, cudaFuncAttributeMaxDynamicSharedMemorySize, SMEM_BYTES);
    cudaFuncSetAttribute(mma_gemm<1>, cudaFuncAttributeMaxDynamicSharedMemorySize, SMEM_BYTES);
    cudaFuncSetAttribute(mma_gemm<2>, cudaFuncAttributeMaxDynamicSharedMemorySize, SMEM_BYTES);

    // 0) tf32-round inputs (+ K-major transposed B operands)
    round_kernel<<<(B_ * S_ * D_ / 4 + 255) / 256, 256>>>(h, hr, B_ * S_ * D_ / 4);
    roundT_kernel<<<dim3(D_ / 32, S_ / 32, B_), dim3(32, 8)>>>(h,  hrT, S_, D_);  // [S,D]->[D,S]
    roundT_kernel<<<dim3(F_ / 32, D_ / 32, 1), dim3(32, 8)>>>(w1, w1t, D_, F_);   // [D,F]->[F,D]
    roundT_kernel<<<dim3(D_ / 32, F_ / 32, 1), dim3(32, 8)>>>(w2, w2t, F_, D_);   // [F,D]->[D,F]

    // 1) scores = (h @ h^T) / sqrt(D):  A=hr[S,D], B=hr[S,D]
    mma_gemm<0><<<dim3(S_ / 128, S_ / 128, B_), 256, SMEM_BYTES>>>(
        hr, hr, scores, S_, S_, D_,
        (size_t)S_ * D_, (size_t)S_ * D_, (size_t)S_ * S_, nullptr, 0.03125f);

    // 2) probs = tf32r(softmax(scores + mask))  (in place)
    softmax_kernel<<<B_ * S_, 256>>>(scores, msk);

    // 3) attn = probs @ h:  A=probs[S,S], B=hrT[D,S]
    mma_gemm<0><<<dim3(D_ / 128, S_ / 128, B_), 256, SMEM_BYTES>>>(
        scores, hrT, attn, S_, D_, S_,
        (size_t)S_ * S_, (size_t)D_ * S_, (size_t)S_ * D_, nullptr, 1.0f);

    // 4) x = LN1(h + attn)  (+ tf32 copy)
    add_ln_kernel<true><<<B_ * S_, 256>>>(h, attn, g1, be1, x, xr);

    // 5) y = tf32r(gelu(x @ w1 + b1)):  A=xr[8192,1024], B=w1t[4096,1024]
    mma_gemm<1><<<dim3(F_ / 128, (B_ * S_) / 128, 1), 256, SMEM_BYTES>>>(
        xr, w1t, y, B_ * S_, F_, D_, 0, 0, 0, b1, 1.0f);

    // 6) f = y @ w2 + b2:  A=y[8192,4096], B=w2t[1024,4096]
    mma_gemm<2><<<dim3(D_ / 128, (B_ * S_) / 128, 1), 256, SMEM_BYTES>>>(
        y, w2t, f, B_ * S_, D_, F_, 0, 0, 0, b2, 1.0f);

    // 7) out = LN2(x + f)
    add_ln_kernel<false><<<B_ * S_, 256>>>(x, f, g2, be2, out, nullptr);
}

// round 10
// speedup vs baseline: 1.4739x; 1.1812x over previous
#include <cuda_runtime.h>
#include <cuda_bf16.h>
#include <math.h>
#include <stdint.h>

#define B_ 4
#define S_ 2048
#define D_ 1024
#define F_ 4096

// ---------------- scratch (device globals: allocation-free) ----------------
__device__ float g_scores[(size_t)B_ * S_ * S_];            //  64 MB fp32 scores
__device__ __nv_bfloat16 g_probsb[(size_t)B_ * S_ * S_];    //  32 MB bf16 probs
__device__ float g_attn  [(size_t)B_ * S_ * D_];            //  32 MB
__device__ float g_x     [(size_t)B_ * S_ * D_];            //  32 MB exact LN1 out
__device__ float g_xr    [(size_t)B_ * S_ * D_];            //  32 MB tf32-rounded LN1 out
__device__ float g_y     [(size_t)B_ * S_ * F_];            // 128 MB tf32-rounded gelu out
__device__ float g_f     [(size_t)B_ * S_ * D_];            //  32 MB
__device__ __nv_bfloat16 g_hb [(size_t)B_ * S_ * D_];       //  16 MB bf16 h  [B,S,D]
__device__ __nv_bfloat16 g_hbT[(size_t)B_ * D_ * S_];       //  16 MB bf16 h^T [B,D,S]
__device__ float g_w1t   [(size_t)F_ * D_];                 //  16 MB tf32 w1^T [F,D]
__device__ float g_w2t   [(size_t)D_ * F_];                 //  16 MB tf32 w2^T [D,F]

// ---------------- helpers ----------------
__device__ __forceinline__ float tf32r(float x) {
    uint32_t u;
    asm("cvt.rna.tf32.f32 %0, %1;" : "=r"(u) : "f"(x));
    return __uint_as_float(u);
}
__device__ __forceinline__ float gelu_exact(float x) {
    return 0.5f * x * (1.0f + erff(x * 0.7071067811865476f));
}
__device__ __forceinline__ float warpSum(float v) {
#pragma unroll
    for (int o = 16; o; o >>= 1) v += __shfl_xor_sync(0xffffffffu, v, o);
    return v;
}
__device__ __forceinline__ float warpMax(float v) {
#pragma unroll
    for (int o = 16; o; o >>= 1) v = fmaxf(v, __shfl_xor_sync(0xffffffffu, v, o));
    return v;
}
__device__ __forceinline__ void mma8(float* c, const uint32_t* a, uint32_t b0, uint32_t b1) {
    asm volatile(
        "mma.sync.aligned.m16n8k8.row.col.f32.tf32.tf32.f32 "
        "{%0,%1,%2,%3}, {%4,%5,%6,%7}, {%8,%9}, {%0,%1,%2,%3};"
        : "+f"(c[0]), "+f"(c[1]), "+f"(c[2]), "+f"(c[3])
        : "r"(a[0]), "r"(a[1]), "r"(a[2]), "r"(a[3]), "r"(b0), "r"(b1));
}
__device__ __forceinline__ void mma16bf(float* c, const uint32_t* a, uint32_t b0, uint32_t b1) {
    asm volatile(
        "mma.sync.aligned.m16n8k16.row.col.f32.bf16.bf16.f32 "
        "{%0,%1,%2,%3}, {%4,%5,%6,%7}, {%8,%9}, {%0,%1,%2,%3};"
        : "+f"(c[0]), "+f"(c[1]), "+f"(c[2]), "+f"(c[3])
        : "r"(a[0]), "r"(a[1]), "r"(a[2]), "r"(a[3]), "r"(b0), "r"(b1));
}
__device__ __forceinline__ void ldsm4(uint32_t& r0, uint32_t& r1, uint32_t& r2, uint32_t& r3,
                                      uint32_t addr) {
    asm volatile("ldmatrix.sync.aligned.m8n8.x4.shared.b16 {%0,%1,%2,%3}, [%4];"
                 : "=r"(r0), "=r"(r1), "=r"(r2), "=r"(r3) : "r"(addr));
}
__device__ __forceinline__ void cpasync16(uint32_t s, const void* g) {
    asm volatile("cp.async.cg.shared.global [%0], [%1], 16;" :: "r"(s), "l"(g));
}
__device__ __forceinline__ void cp_commit() { asm volatile("cp.async.commit_group;"); }
template <int N>
__device__ __forceinline__ void cp_wait() {
    asm volatile("cp.async.wait_group %0;" :: "n"(N));
}

// ---------------- tf32 rounding pass ----------------
__global__ void round_kernel(const float* __restrict__ src, float* __restrict__ dst, int n4) {
    int i = blockIdx.x * blockDim.x + threadIdx.x;
    if (i < n4) {
        float4 v = ((const float4*)src)[i];
        v.x = tf32r(v.x); v.y = tf32r(v.y); v.z = tf32r(v.z); v.w = tf32r(v.w);
        ((float4*)dst)[i] = v;
    }
}

// ---------------- round + transpose (tf32): src[z][R][C] -> dst[z][C][R] ----------
__global__ void roundT_kernel(const float* __restrict__ src, float* __restrict__ dst,
                              int R, int C) {
    __shared__ float t[32][33];
    src += (size_t)blockIdx.z * R * C;
    dst += (size_t)blockIdx.z * R * C;
    const int r0 = blockIdx.y * 32, c0 = blockIdx.x * 32;
    const int tx = threadIdx.x, ty = threadIdx.y;   // 32 x 8
#pragma unroll
    for (int i = 0; i < 32; i += 8)
        t[ty + i][tx] = tf32r(src[(size_t)(r0 + ty + i) * C + c0 + tx]);
    __syncthreads();
#pragma unroll
    for (int i = 0; i < 32; i += 8)
        dst[(size_t)(c0 + ty + i) * R + r0 + tx] = t[tx][ty + i];
}

// ---------------- f32 -> bf16 convert ----------------
__global__ void cvtB_kernel(const float* __restrict__ src, __nv_bfloat16* __restrict__ dst,
                            int n8) {
    int i = blockIdx.x * blockDim.x + threadIdx.x;
    if (i < n8) {
        float4 v0 = ((const float4*)src)[2 * i];
        float4 v1 = ((const float4*)src)[2 * i + 1];
        __nv_bfloat162 b0 = __float22bfloat162_rn(make_float2(v0.x, v0.y));
        __nv_bfloat162 b1 = __float22bfloat162_rn(make_float2(v0.z, v0.w));
        __nv_bfloat162 b2 = __float22bfloat162_rn(make_float2(v1.x, v1.y));
        __nv_bfloat162 b3 = __float22bfloat162_rn(make_float2(v1.z, v1.w));
        uint4 o;
        o.x = *(uint32_t*)&b0; o.y = *(uint32_t*)&b1;
        o.z = *(uint32_t*)&b2; o.w = *(uint32_t*)&b3;
        ((uint4*)dst)[i] = o;
    }
}

// ---------------- f32 -> bf16 transpose convert: src[z][R][C] -> dst[z][C][R] ------
__global__ void cvtBT_kernel(const float* __restrict__ src, __nv_bfloat16* __restrict__ dst,
                             int R, int C) {
    __shared__ float t[32][33];
    src += (size_t)blockIdx.z * R * C;
    dst += (size_t)blockIdx.z * R * C;
    const int r0 = blockIdx.y * 32, c0 = blockIdx.x * 32;
    const int tx = threadIdx.x, ty = threadIdx.y;   // 32 x 8
#pragma unroll
    for (int i = 0; i < 32; i += 8)
        t[ty + i][tx] = src[(size_t)(r0 + ty + i) * C + c0 + tx];
    __syncthreads();
#pragma unroll
    for (int i = 0; i < 32; i += 8)
        dst[(size_t)(c0 + ty + i) * R + r0 + tx] = __float2bfloat16(t[tx][ty + i]);
}

#define STAGE_B 16384                       // 128 rows x 128 B
#define SMEM_BYTES (3 * 2 * STAGE_B)        // 98304 B

// ---------------- TF32 mma.sync GEMM (ldmatrix + cp.async), as round 8 -------------
// C[M,N] = epi( A[M,K] @ B[N,K]^T ), A,B tf32-pre-rounded fp32, K%32==0.
template <int EPI>
__global__ void __launch_bounds__(256, 2)
mma_gemm(const float* __restrict__ A, const float* __restrict__ B,
         float* __restrict__ C, int M, int N, int K,
         size_t sA, size_t sB, size_t sC,
         const float* __restrict__ bias, float alpha) {
    extern __shared__ float sm[];
    const uint32_t sb = (uint32_t)__cvta_generic_to_shared(sm);

    A += (size_t)blockIdx.z * sA;
    B += (size_t)blockIdx.z * sB;
    C += (size_t)blockIdx.z * sC;

    const int tid  = threadIdx.x;
    const int lane = tid & 31, warp = tid >> 5;
    const int wm = warp >> 2, wn = warp & 3;

    const int arow = tid >> 1;
    const int ac4  = (tid & 1) * 4;
    const float* Ag = A + (size_t)(blockIdx.y * 128 + arow) * K + (tid & 1) * 16;
    const float* Bg = B + (size_t)(blockIdx.x * 128 + arow) * K + (tid & 1) * 16;
    const uint32_t aRow = sb + (uint32_t)arow * 128;
    const uint32_t bRow = sb + 3 * STAGE_B + (uint32_t)arow * 128;
    const int rsw = arow & 7;

    auto issue = [&](int ch, int s) {
        const float* ag = Ag + ch * 32;
        const float* bg = Bg + ch * 32;
        const uint32_t as = aRow + s * STAGE_B;
        const uint32_t bs = bRow + s * STAGE_B;
#pragma unroll
        for (int j = 0; j < 4; j++) {
            const uint32_t off = (uint32_t)(((ac4 + j) ^ rsw) * 16);
            cpasync16(as + off, ag + j * 4);
            cpasync16(bs + off, bg + j * 4);
        }
    };

    const int lm = lane >> 3, ri = lane & 7;
    uint32_t aOff[4]; int aSel[4];
#pragma unroll
    for (int mt = 0; mt < 4; mt++) {
        const int r = wm * 64 + mt * 16 + (lm & 1) * 8 + ri;
        aOff[mt] = (uint32_t)r * 128;
        aSel[mt] = r & 7;
    }
    const int aCh = lm >> 1;
    uint32_t bOff[2]; int bSel[2];
#pragma unroll
    for (int np = 0; np < 2; np++) {
        const int r = wn * 32 + np * 16 + (lm >> 1) * 8 + ri;
        bOff[np] = (uint32_t)r * 128;
        bSel[np] = r & 7;
    }
    const int bCh = lm & 1;

    const int nch = K >> 5;

    issue(0, 0); cp_commit();
    issue(1, 1); cp_commit();

    float acc[4][4][4];
#pragma unroll
    for (int i = 0; i < 4; i++)
#pragma unroll
        for (int j = 0; j < 4; j++)
#pragma unroll
            for (int p = 0; p < 4; p++) acc[i][j][p] = 0.f;

    for (int ch = 0; ch < nch; ch++) {
        const int s = ch % 3;
        cp_wait<1>();
        __syncthreads();

        if (ch + 2 < nch) issue(ch + 2, (ch + 2) % 3);
        cp_commit();

        const uint32_t aSt = sb + s * STAGE_B;
        const uint32_t bSt = sb + 3 * STAGE_B + s * STAGE_B;

#pragma unroll
        for (int ks = 0; ks < 4; ks++) {
            uint32_t a[4][4];
#pragma unroll
            for (int mt = 0; mt < 4; mt++)
                ldsm4(a[mt][0], a[mt][1], a[mt][2], a[mt][3],
                      aSt + aOff[mt] + (uint32_t)(((2 * ks + aCh) ^ aSel[mt]) << 4));
            uint32_t bb[2][4];
#pragma unroll
            for (int np = 0; np < 2; np++)
                ldsm4(bb[np][0], bb[np][1], bb[np][2], bb[np][3],
                      bSt + bOff[np] + (uint32_t)(((2 * ks + bCh) ^ bSel[np]) << 4));
#pragma unroll
            for (int nt = 0; nt < 4; nt++) {
                const uint32_t b0 = bb[nt >> 1][(nt & 1) * 2];
                const uint32_t b1 = bb[nt >> 1][(nt & 1) * 2 + 1];
#pragma unroll
                for (int mt = 0; mt < 4; mt++) mma8(acc[mt][nt], a[mt], b0, b1);
            }
        }
    }

    const int g = lane >> 2, tig = lane & 3;
#pragma unroll
    for (int mt = 0; mt < 4; mt++) {
        const int r0 = blockIdx.y * 128 + wm * 64 + mt * 16 + g;
#pragma unroll
        for (int nt = 0; nt < 4; nt++) {
            const int c0 = blockIdx.x * 128 + wn * 32 + nt * 8 + 2 * tig;
            float v0 = acc[mt][nt][0], v1 = acc[mt][nt][1];
            float v2 = acc[mt][nt][2], v3 = acc[mt][nt][3];
            if (EPI == 0) {
                v0 *= alpha; v1 *= alpha; v2 *= alpha; v3 *= alpha;
            } else {
                const float bb0 = bias[c0], bb1 = bias[c0 + 1];
                v0 += bb0; v1 += bb1; v2 += bb0; v3 += bb1;
                if (EPI == 1) {
                    v0 = tf32r(gelu_exact(v0)); v1 = tf32r(gelu_exact(v1));
                    v2 = tf32r(gelu_exact(v2)); v3 = tf32r(gelu_exact(v3));
                }
            }
            *(float2*)(C + (size_t)r0 * N + c0)       = make_float2(v0, v1);
            *(float2*)(C + (size_t)(r0 + 8) * N + c0) = make_float2(v2, v3);
        }
    }
}

// ---------------- BF16 mma.sync GEMM (m16n8k16), K-chunk 64 ----------------
// C[M,N] = alpha * (A[M,K] @ B[N,K]^T), A,B bf16, K%64==0.
// Same 128x128 block / 8-warp layout; tile rows = 64 bf16 = 128 B.
__global__ void __launch_bounds__(256, 2)
bf_gemm(const __nv_bfloat16* __restrict__ A, const __nv_bfloat16* __restrict__ B,
        float* __restrict__ C, int M, int N, int K,
        size_t sA, size_t sB, size_t sC, float alpha) {
    extern __shared__ float sm[];
    const uint32_t sb = (uint32_t)__cvta_generic_to_shared(sm);

    A += (size_t)blockIdx.z * sA;
    B += (size_t)blockIdx.z * sB;
    C += (size_t)blockIdx.z * sC;

    const int tid  = threadIdx.x;
    const int lane = tid & 31, warp = tid >> 5;
    const int wm = warp >> 2, wn = warp & 3;

    const int arow = tid >> 1;
    const int ac4  = (tid & 1) * 4;
    const __nv_bfloat16* Ag = A + (size_t)(blockIdx.y * 128 + arow) * K + (tid & 1) * 32;
    const __nv_bfloat16* Bg = B + (size_t)(blockIdx.x * 128 + arow) * K + (tid & 1) * 32;
    const uint32_t aRow = sb + (uint32_t)arow * 128;
    const uint32_t bRow = sb + 3 * STAGE_B + (uint32_t)arow * 128;
    const int rsw = arow & 7;

    auto issue = [&](int ch, int s) {
        const __nv_bfloat16* ag = Ag + ch * 64;
        const __nv_bfloat16* bg = Bg + ch * 64;
        const uint32_t as = aRow + s * STAGE_B;
        const uint32_t bs = bRow + s * STAGE_B;
#pragma unroll
        for (int j = 0; j < 4; j++) {
            const uint32_t off = (uint32_t)(((ac4 + j) ^ rsw) * 16);
            cpasync16(as + off, ag + j * 8);
            cpasync16(bs + off, bg + j * 8);
        }
    };

    // ldmatrix lane mapping
    const int lm = lane >> 3, ri = lane & 7;
    // A 16x16 frag: matrices (rows0-7,k0-7),(rows8-15,k0-7),(rows0-7,k8-15),(rows8-15,k8-15)
    uint32_t aOff[4]; int aSel[4];
#pragma unroll
    for (int mt = 0; mt < 4; mt++) {
        const int r = wm * 64 + mt * 16 + (lm & 1) * 8 + ri;
        aOff[mt] = (uint32_t)r * 128;
        aSel[mt] = r & 7;
    }
    const int aCh = lm >> 1;                 // 16B chunk within k16 (0/1)
    // B: one x4 covers 2 n8-tiles x (k0-7,k8-15)
    uint32_t bOff[2]; int bSel[2];
#pragma unroll
    for (int np = 0; np < 2; np++) {
        const int r = wn * 32 + np * 16 + (lm >> 1) * 8 + ri;
        bOff[np] = (uint32_t)r * 128;
        bSel[np] = r & 7;
    }
    const int bCh = lm & 1;

    const int nch = K >> 6;                  // K-chunk = 64 bf16

    issue(0, 0); cp_commit();
    issue(1, 1); cp_commit();

    float acc[4][4][4];
#pragma unroll
    for (int i = 0; i < 4; i++)
#pragma unroll
        for (int j = 0; j < 4; j++)
#pragma unroll
            for (int p = 0; p < 4; p++) acc[i][j][p] = 0.f;

    for (int ch = 0; ch < nch; ch++) {
        const int s = ch % 3;
        cp_wait<1>();
        __syncthreads();

        if (ch + 2 < nch) issue(ch + 2, (ch + 2) % 3);
        cp_commit();

        const uint32_t aSt = sb + s * STAGE_B;
        const uint32_t bSt = sb + 3 * STAGE_B + s * STAGE_B;

#pragma unroll
        for (int ks = 0; ks < 4; ks++) {     // 4 x k16 per chunk
            uint32_t a[4][4];
#pragma unroll
            for (int mt = 0; mt < 4; mt++)
                ldsm4(a[mt][0], a[mt][1], a[mt][2], a[mt][3],
                      aSt + aOff[mt] + (uint32_t)(((2 * ks + aCh) ^ aSel[mt]) << 4));
            uint32_t bb[2][4];
#pragma unroll
            for (int np = 0; np < 2; np++)
                ldsm4(bb[np][0], bb[np][1], bb[np][2], bb[np][3],
                      bSt + bOff[np] + (uint32_t)(((2 * ks + bCh) ^ bSel[np]) << 4));
#pragma unroll
            for (int nt = 0; nt < 4; nt++) {
                const uint32_t b0 = bb[nt >> 1][(nt & 1) * 2];
                const uint32_t b1 = bb[nt >> 1][(nt & 1) * 2 + 1];
#pragma unroll
                for (int mt = 0; mt < 4; mt++) mma16bf(acc[mt][nt], a[mt], b0, b1);
            }
        }
    }

    const int g = lane >> 2, tig = lane & 3;
#pragma unroll
    for (int mt = 0; mt < 4; mt++) {
        const int r0 = blockIdx.y * 128 + wm * 64 + mt * 16 + g;
#pragma unroll
        for (int nt = 0; nt < 4; nt++) {
            const int c0 = blockIdx.x * 128 + wn * 32 + nt * 8 + 2 * tig;
            float v0 = acc[mt][nt][0] * alpha, v1 = acc[mt][nt][1] * alpha;
            float v2 = acc[mt][nt][2] * alpha, v3 = acc[mt][nt][3] * alpha;
            *(float2*)(C + (size_t)r0 * N + c0)       = make_float2(v0, v1);
            *(float2*)(C + (size_t)(r0 + 8) * N + c0) = make_float2(v2, v3);
        }
    }
}

// ---------------- softmax: fp32 scores + mask -> bf16 probs ----------------
__global__ void softmax_kernel(const float* __restrict__ P, __nv_bfloat16* __restrict__ Pb,
                               const float* __restrict__ mask) {
    __shared__ float sh[8];
    const int row = blockIdx.x;
    const int b   = row >> 11;
    const float* p = P + (size_t)row * S_;
    __nv_bfloat16* pb = Pb + (size_t)row * S_;
    const float* m = mask + (size_t)b * S_;
    const int tid = threadIdx.x;

    float v[8];
    float mx = -1e30f;
#pragma unroll
    for (int i = 0; i < 8; i++) {
        const int idx = tid + (i << 8);
        v[i] = p[idx] + m[idx];
        mx = fmaxf(mx, v[i]);
    }
    mx = warpMax(mx);
    if ((tid & 31) == 0) sh[tid >> 5] = mx;
    __syncthreads();
    mx = sh[0];
#pragma unroll
    for (int j = 1; j < 8; j++) mx = fmaxf(mx, sh[j]);

    float s = 0.f;
#pragma unroll
    for (int i = 0; i < 8; i++) { v[i] = expf(v[i] - mx); s += v[i]; }
    s = warpSum(s);
    __syncthreads();
    if ((tid & 31) == 0) sh[tid >> 5] = s;
    __syncthreads();
    s = 0.f;
#pragma unroll
    for (int j = 0; j < 8; j++) s += sh[j];
    const float inv = 1.0f / s;
#pragma unroll
    for (int i = 0; i < 8; i++) pb[tid + (i << 8)] = __float2bfloat16(v[i] * inv);
}

// ---------------- out = LayerNorm(X + Y); optionally also tf32-rounded copy ----
template <bool WR>
__global__ void add_ln_kernel(const float* __restrict__ X, const float* __restrict__ Y,
                              const float* __restrict__ gamma, const float* __restrict__ beta,
                              float* __restrict__ O, float* __restrict__ OR_) {
    __shared__ float shs[8], shq[8];
    const int row = blockIdx.x;
    const int tid = threadIdx.x;
    const size_t base = (size_t)row * D_ + tid * 4;

    const float4 a = *(const float4*)(X + base);
    const float4 b = *(const float4*)(Y + base);
    const float v0 = a.x + b.x, v1 = a.y + b.y, v2 = a.z + b.z, v3 = a.w + b.w;

    float s = v0 + v1 + v2 + v3;
    float q = v0 * v0 + v1 * v1 + v2 * v2 + v3 * v3;
    s = warpSum(s); q = warpSum(q);
    if ((tid & 31) == 0) { shs[tid >> 5] = s; shq[tid >> 5] = q; }
    __syncthreads();
    s = 0.f; q = 0.f;
#pragma unroll
    for (int j = 0; j < 8; j++) { s += shs[j]; q += shq[j]; }
    const float mean = s * (1.0f / D_);
    const float var  = q * (1.0f / D_) - mean * mean;
    const float rstd = rsqrtf(var + 1e-5f);

    const float4 gm = *(const float4*)(gamma + tid * 4);
    const float4 bt = *(const float4*)(beta  + tid * 4);
    float4 o;
    o.x = (v0 - mean) * rstd * gm.x + bt.x;
    o.y = (v1 - mean) * rstd * gm.y + bt.y;
    o.z = (v2 - mean) * rstd * gm.z + bt.z;
    o.w = (v3 - mean) * rstd * gm.w + bt.w;
    *(float4*)(O + base) = o;
    if (WR) {
        float4 rr;
        rr.x = tf32r(o.x); rr.y = tf32r(o.y); rr.z = tf32r(o.z); rr.w = tf32r(o.w);
        *(float4*)(OR_ + base) = rr;
    }
}

// ---------------- launch ----------------
extern "C" void kernel_launch(void* const* d_in, const int* in_sizes, int n_in,
                              void* d_out, int out_size) {
    const float* h   = (const float*)d_in[0];
    const float* msk = (const float*)d_in[1];
    const float* w1  = (const float*)d_in[2];
    const float* b1  = (const float*)d_in[3];
    const float* w2  = (const float*)d_in[4];
    const float* b2  = (const float*)d_in[5];
    const float* g1  = (const float*)d_in[6];
    const float* be1 = (const float*)d_in[7];
    const float* g2  = (const float*)d_in[8];
    const float* be2 = (const float*)d_in[9];
    float* out = (float*)d_out;

    float *scores, *attn, *x, *xr, *y, *f, *w1t, *w2t;
    __nv_bfloat16 *probsb, *hb, *hbT;
    cudaGetSymbolAddress((void**)&scores, g_scores);
    cudaGetSymbolAddress((void**)&probsb, g_probsb);
    cudaGetSymbolAddress((void**)&attn,   g_attn);
    cudaGetSymbolAddress((void**)&x,      g_x);
    cudaGetSymbolAddress((void**)&xr,     g_xr);
    cudaGetSymbolAddress((void**)&y,      g_y);
    cudaGetSymbolAddress((void**)&f,      g_f);
    cudaGetSymbolAddress((void**)&hb,     g_hb);
    cudaGetSymbolAddress((void**)&hbT,    g_hbT);
    cudaGetSymbolAddress((void**)&w1t,    g_w1t);
    cudaGetSymbolAddress((void**)&w2t,    g_w2t);

    cudaFuncSetAttribute(mma_gemm<1>, cudaFuncAttributeMaxDynamicSharedMemorySize, SMEM_BYTES);
    cudaFuncSetAttribute(mma_gemm<2>, cudaFuncAttributeMaxDynamicSharedMemorySize, SMEM_BYTES);
    cudaFuncSetAttribute(bf_gemm,     cudaFuncAttributeMaxDynamicSharedMemorySize, SMEM_BYTES);

    // 0) convert inputs: bf16 h / h^T for attention; tf32 w^T for FFN
    cvtB_kernel<<<(B_ * S_ * D_ / 8 + 255) / 256, 256>>>(h, hb, B_ * S_ * D_ / 8);
    cvtBT_kernel<<<dim3(D_ / 32, S_ / 32, B_), dim3(32, 8)>>>(h, hbT, S_, D_);   // [S,D]->[D,S]
    roundT_kernel<<<dim3(F_ / 32, D_ / 32, 1), dim3(32, 8)>>>(w1, w1t, D_, F_);  // [D,F]->[F,D]
    roundT_kernel<<<dim3(D_ / 32, F_ / 32, 1), dim3(32, 8)>>>(w2, w2t, F_, D_);  // [F,D]->[D,F]

    // 1) scores = (h @ h^T) / sqrt(D)   (bf16 tensor cores)
    bf_gemm<<<dim3(S_ / 128, S_ / 128, B_), 256, SMEM_BYTES>>>(
        hb, hb, scores, S_, S_, D_,
        (size_t)S_ * D_, (size_t)S_ * D_, (size_t)S_ * S_, 0.03125f);

    // 2) probs(bf16) = softmax(scores + mask)
    softmax_kernel<<<B_ * S_, 256>>>(scores, probsb, msk);

    // 3) attn = probs @ h   (bf16 tensor cores)
    bf_gemm<<<dim3(D_ / 128, S_ / 128, B_), 256, SMEM_BYTES>>>(
        probsb, hbT, attn, S_, D_, S_,
        (size_t)S_ * S_, (size_t)D_ * S_, (size_t)S_ * D_, 1.0f);

    // 4) x = LN1(h + attn)  (+ tf32 copy)
    add_ln_kernel<true><<<B_ * S_, 256>>>(h, attn, g1, be1, x, xr);

    // 5) y = tf32r(gelu(x @ w1 + b1))   (tf32)
    mma_gemm<1><<<dim3(F_ / 128, (B_ * S_) / 128, 1), 256, SMEM_BYTES>>>(
        xr, w1t, y, B_ * S_, F_, D_, 0, 0, 0, b1, 1.0f);

    // 6) f = y @ w2 + b2   (tf32)
    mma_gemm<2><<<dim3(D_ / 128, (B_ * S_) / 128, 1), 256, SMEM_BYTES>>>(
        y, w2t, f, B_ * S_, D_, F_, 0, 0, 0, b2, 1.0f);

    // 7) out = LN2(x + f)
    add_ln_kernel<false><<<B_ * S_, 256>>>(x, f, g2, be2, out, nullptr);
}

// round 11
// speedup vs baseline: 2.2868x; 1.5515x over previous
#include <cuda_runtime.h>
#include <cuda_fp16.h>
#include <math.h>
#include <stdint.h>

#define B_ 4
#define S_ 2048
#define D_ 1024
#define F_ 4096

// ---------------- scratch (device globals: allocation-free) ----------------
__device__ float  g_scores[(size_t)B_ * S_ * S_];      //  64 MB fp32 scores
__device__ __half g_probsh[(size_t)B_ * S_ * S_];      //  32 MB fp16 probs
__device__ float  g_attn  [(size_t)B_ * S_ * D_];      //  32 MB
__device__ float  g_x     [(size_t)B_ * S_ * D_];      //  32 MB exact LN1 out
__device__ __half g_xh    [(size_t)B_ * S_ * D_];      //  16 MB fp16 LN1 out
__device__ __half g_y     [(size_t)B_ * S_ * F_];      //  64 MB fp16 gelu out
__device__ float  g_f     [(size_t)B_ * S_ * D_];      //  32 MB
__device__ __half g_hh    [(size_t)B_ * S_ * D_];      //  16 MB fp16 h   [B,S,D]
__device__ __half g_hhT   [(size_t)B_ * D_ * S_];      //  16 MB fp16 h^T [B,D,S]
__device__ __half g_w1t   [(size_t)F_ * D_];           //   8 MB fp16 w1^T [F,D]
__device__ __half g_w2t   [(size_t)D_ * F_];           //   8 MB fp16 w2^T [D,F]

// ---------------- helpers ----------------
__device__ __forceinline__ float gelu_exact(float x) {
    return 0.5f * x * (1.0f + erff(x * 0.7071067811865476f));
}
__device__ __forceinline__ float warpSum(float v) {
#pragma unroll
    for (int o = 16; o; o >>= 1) v += __shfl_xor_sync(0xffffffffu, v, o);
    return v;
}
__device__ __forceinline__ float warpMax(float v) {
#pragma unroll
    for (int o = 16; o; o >>= 1) v = fmaxf(v, __shfl_xor_sync(0xffffffffu, v, o));
    return v;
}
__device__ __forceinline__ void mma16f(float* c, const uint32_t* a, uint32_t b0, uint32_t b1) {
    asm volatile(
        "mma.sync.aligned.m16n8k16.row.col.f32.f16.f16.f32 "
        "{%0,%1,%2,%3}, {%4,%5,%6,%7}, {%8,%9}, {%0,%1,%2,%3};"
        : "+f"(c[0]), "+f"(c[1]), "+f"(c[2]), "+f"(c[3])
        : "r"(a[0]), "r"(a[1]), "r"(a[2]), "r"(a[3]), "r"(b0), "r"(b1));
}
__device__ __forceinline__ void ldsm4(uint32_t& r0, uint32_t& r1, uint32_t& r2, uint32_t& r3,
                                      uint32_t addr) {
    asm volatile("ldmatrix.sync.aligned.m8n8.x4.shared.b16 {%0,%1,%2,%3}, [%4];"
                 : "=r"(r0), "=r"(r1), "=r"(r2), "=r"(r3) : "r"(addr));
}
__device__ __forceinline__ void cpasync16(uint32_t s, const void* g) {
    asm volatile("cp.async.cg.shared.global [%0], [%1], 16;" :: "r"(s), "l"(g));
}
__device__ __forceinline__ void cp_commit() { asm volatile("cp.async.commit_group;"); }
template <int N>
__device__ __forceinline__ void cp_wait() {
    asm volatile("cp.async.wait_group %0;" :: "n"(N));
}

// ---------------- f32 -> fp16 convert ----------------
__global__ void cvtH_kernel(const float* __restrict__ src, __half* __restrict__ dst, int n8) {
    int i = blockIdx.x * blockDim.x + threadIdx.x;
    if (i < n8) {
        float4 v0 = ((const float4*)src)[2 * i];
        float4 v1 = ((const float4*)src)[2 * i + 1];
        __half2 h0 = __floats2half2_rn(v0.x, v0.y);
        __half2 h1 = __floats2half2_rn(v0.z, v0.w);
        __half2 h2 = __floats2half2_rn(v1.x, v1.y);
        __half2 h3 = __floats2half2_rn(v1.z, v1.w);
        uint4 o;
        o.x = *(uint32_t*)&h0; o.y = *(uint32_t*)&h1;
        o.z = *(uint32_t*)&h2; o.w = *(uint32_t*)&h3;
        ((uint4*)dst)[i] = o;
    }
}

// ---------------- f32 -> fp16 transpose convert: src[z][R][C] -> dst[z][C][R] ------
__global__ void cvtHT_kernel(const float* __restrict__ src, __half* __restrict__ dst,
                             int R, int C) {
    __shared__ float t[32][33];
    src += (size_t)blockIdx.z * R * C;
    dst += (size_t)blockIdx.z * R * C;
    const int r0 = blockIdx.y * 32, c0 = blockIdx.x * 32;
    const int tx = threadIdx.x, ty = threadIdx.y;   // 32 x 8
#pragma unroll
    for (int i = 0; i < 32; i += 8)
        t[ty + i][tx] = src[(size_t)(r0 + ty + i) * C + c0 + tx];
    __syncthreads();
#pragma unroll
    for (int i = 0; i < 32; i += 8)
        dst[(size_t)(c0 + ty + i) * R + r0 + tx] = __float2half(t[tx][ty + i]);
}

#define STAGE_B 16384                       // 128 rows x 128 B
#define SMEM_BYTES (3 * 2 * STAGE_B)        // 98304 B

// ---------------- FP16 mma.sync GEMM (m16n8k16), K-chunk 64 ----------------
// C[M,N] = epi( A[M,K] @ B[N,K]^T ), A,B fp16 K-major, K%64==0.
// 128x128 block, 256 threads, 8 warps (2x4) of 64x32, 3-stage cp.async,
// XOR-swizzled 128B tile rows, ldmatrix feeds.
// EPI: 0 -> fp32 C = acc*alpha
//      1 -> fp16 C = gelu(acc + bias[col])
//      2 -> fp32 C = acc + bias[col]
template <int EPI>
__global__ void __launch_bounds__(256, 2)
hf_gemm(const __half* __restrict__ A, const __half* __restrict__ B,
        void* __restrict__ Cv, int M, int N, int K,
        size_t sA, size_t sB, size_t sC,
        const float* __restrict__ bias, float alpha) {
    extern __shared__ float sm[];
    const uint32_t sb = (uint32_t)__cvta_generic_to_shared(sm);

    A += (size_t)blockIdx.z * sA;
    B += (size_t)blockIdx.z * sB;

    const int tid  = threadIdx.x;
    const int lane = tid & 31, warp = tid >> 5;
    const int wm = warp >> 2, wn = warp & 3;

    // cp.async mapping: thread t -> tile row t>>1, 4 x 16B chunks
    const int arow = tid >> 1;
    const int ac4  = (tid & 1) * 4;
    const __half* Ag = A + (size_t)(blockIdx.y * 128 + arow) * K + (tid & 1) * 32;
    const __half* Bg = B + (size_t)(blockIdx.x * 128 + arow) * K + (tid & 1) * 32;
    const uint32_t aRow = sb + (uint32_t)arow * 128;
    const uint32_t bRow = sb + 3 * STAGE_B + (uint32_t)arow * 128;
    const int rsw = arow & 7;

    auto issue = [&](int ch, int s) {
        const __half* ag = Ag + ch * 64;
        const __half* bg = Bg + ch * 64;
        const uint32_t as = aRow + s * STAGE_B;
        const uint32_t bs = bRow + s * STAGE_B;
#pragma unroll
        for (int j = 0; j < 4; j++) {
            const uint32_t off = (uint32_t)(((ac4 + j) ^ rsw) * 16);
            cpasync16(as + off, ag + j * 8);
            cpasync16(bs + off, bg + j * 8);
        }
    };

    // ldmatrix lane mapping
    const int lm = lane >> 3, ri = lane & 7;
    uint32_t aOff[4]; int aSel[4];
#pragma unroll
    for (int mt = 0; mt < 4; mt++) {
        const int r = wm * 64 + mt * 16 + (lm & 1) * 8 + ri;
        aOff[mt] = (uint32_t)r * 128;
        aSel[mt] = r & 7;
    }
    const int aCh = lm >> 1;
    uint32_t bOff[2]; int bSel[2];
#pragma unroll
    for (int np = 0; np < 2; np++) {
        const int r = wn * 32 + np * 16 + (lm >> 1) * 8 + ri;
        bOff[np] = (uint32_t)r * 128;
        bSel[np] = r & 7;
    }
    const int bCh = lm & 1;

    const int nch = K >> 6;

    issue(0, 0); cp_commit();
    issue(1, 1); cp_commit();

    float acc[4][4][4];
#pragma unroll
    for (int i = 0; i < 4; i++)
#pragma unroll
        for (int j = 0; j < 4; j++)
#pragma unroll
            for (int p = 0; p < 4; p++) acc[i][j][p] = 0.f;

    for (int ch = 0; ch < nch; ch++) {
        const int s = ch % 3;
        cp_wait<1>();
        __syncthreads();

        if (ch + 2 < nch) issue(ch + 2, (ch + 2) % 3);
        cp_commit();

        const uint32_t aSt = sb + s * STAGE_B;
        const uint32_t bSt = sb + 3 * STAGE_B + s * STAGE_B;

#pragma unroll
        for (int ks = 0; ks < 4; ks++) {     // 4 x k16 per 64-chunk
            uint32_t a[4][4];
#pragma unroll
            for (int mt = 0; mt < 4; mt++)
                ldsm4(a[mt][0], a[mt][1], a[mt][2], a[mt][3],
                      aSt + aOff[mt] + (uint32_t)(((2 * ks + aCh) ^ aSel[mt]) << 4));
            uint32_t bb[2][4];
#pragma unroll
            for (int np = 0; np < 2; np++)
                ldsm4(bb[np][0], bb[np][1], bb[np][2], bb[np][3],
                      bSt + bOff[np] + (uint32_t)(((2 * ks + bCh) ^ bSel[np]) << 4));
#pragma unroll
            for (int nt = 0; nt < 4; nt++) {
                const uint32_t b0 = bb[nt >> 1][(nt & 1) * 2];
                const uint32_t b1 = bb[nt >> 1][(nt & 1) * 2 + 1];
#pragma unroll
                for (int mt = 0; mt < 4; mt++) mma16f(acc[mt][nt], a[mt], b0, b1);
            }
        }
    }

    // ---- epilogue ----
    const int g = lane >> 2, tig = lane & 3;
#pragma unroll
    for (int mt = 0; mt < 4; mt++) {
        const int r0 = blockIdx.y * 128 + wm * 64 + mt * 16 + g;
#pragma unroll
        for (int nt = 0; nt < 4; nt++) {
            const int c0 = blockIdx.x * 128 + wn * 32 + nt * 8 + 2 * tig;
            float v0 = acc[mt][nt][0], v1 = acc[mt][nt][1];
            float v2 = acc[mt][nt][2], v3 = acc[mt][nt][3];
            if (EPI == 0) {
                float* C = (float*)Cv + (size_t)blockIdx.z * sC;
                v0 *= alpha; v1 *= alpha; v2 *= alpha; v3 *= alpha;
                *(float2*)(C + (size_t)r0 * N + c0)       = make_float2(v0, v1);
                *(float2*)(C + (size_t)(r0 + 8) * N + c0) = make_float2(v2, v3);
            } else {
                const float bb0 = bias[c0], bb1 = bias[c0 + 1];
                v0 += bb0; v1 += bb1; v2 += bb0; v3 += bb1;
                if (EPI == 1) {
                    __half* C = (__half*)Cv + (size_t)blockIdx.z * sC;
                    v0 = gelu_exact(v0); v1 = gelu_exact(v1);
                    v2 = gelu_exact(v2); v3 = gelu_exact(v3);
                    *(__half2*)(C + (size_t)r0 * N + c0)       = __floats2half2_rn(v0, v1);
                    *(__half2*)(C + (size_t)(r0 + 8) * N + c0) = __floats2half2_rn(v2, v3);
                } else {
                    float* C = (float*)Cv + (size_t)blockIdx.z * sC;
                    *(float2*)(C + (size_t)r0 * N + c0)       = make_float2(v0, v1);
                    *(float2*)(C + (size_t)(r0 + 8) * N + c0) = make_float2(v2, v3);
                }
            }
        }
    }
}

// ---------------- softmax: fp32 scores + mask -> fp16 probs ----------------
__global__ void softmax_kernel(const float* __restrict__ P, __half* __restrict__ Ph,
                               const float* __restrict__ mask) {
    __shared__ float sh[8];
    const int row = blockIdx.x;
    const int b   = row >> 11;
    const float* p = P + (size_t)row * S_;
    __half* ph = Ph + (size_t)row * S_;
    const float* m = mask + (size_t)b * S_;
    const int tid = threadIdx.x;

    float v[8];
    float mx = -1e30f;
#pragma unroll
    for (int i = 0; i < 8; i++) {
        const int idx = tid + (i << 8);
        v[i] = p[idx] + m[idx];
        mx = fmaxf(mx, v[i]);
    }
    mx = warpMax(mx);
    if ((tid & 31) == 0) sh[tid >> 5] = mx;
    __syncthreads();
    mx = sh[0];
#pragma unroll
    for (int j = 1; j < 8; j++) mx = fmaxf(mx, sh[j]);

    float s = 0.f;
#pragma unroll
    for (int i = 0; i < 8; i++) { v[i] = expf(v[i] - mx); s += v[i]; }
    s = warpSum(s);
    __syncthreads();
    if ((tid & 31) == 0) sh[tid >> 5] = s;
    __syncthreads();
    s = 0.f;
#pragma unroll
    for (int j = 0; j < 8; j++) s += sh[j];
    const float inv = 1.0f / s;
#pragma unroll
    for (int i = 0; i < 8; i++) ph[tid + (i << 8)] = __float2half(v[i] * inv);
}

// ---------------- out = LayerNorm(X + Y); optionally also fp16 copy ----
template <bool WR>
__global__ void add_ln_kernel(const float* __restrict__ X, const float* __restrict__ Y,
                              const float* __restrict__ gamma, const float* __restrict__ beta,
                              float* __restrict__ O, __half* __restrict__ OH) {
    __shared__ float shs[8], shq[8];
    const int row = blockIdx.x;
    const int tid = threadIdx.x;
    const size_t base = (size_t)row * D_ + tid * 4;

    const float4 a = *(const float4*)(X + base);
    const float4 b = *(const float4*)(Y + base);
    const float v0 = a.x + b.x, v1 = a.y + b.y, v2 = a.z + b.z, v3 = a.w + b.w;

    float s = v0 + v1 + v2 + v3;
    float q = v0 * v0 + v1 * v1 + v2 * v2 + v3 * v3;
    s = warpSum(s); q = warpSum(q);
    if ((tid & 31) == 0) { shs[tid >> 5] = s; shq[tid >> 5] = q; }
    __syncthreads();
    s = 0.f; q = 0.f;
#pragma unroll
    for (int j = 0; j < 8; j++) { s += shs[j]; q += shq[j]; }
    const float mean = s * (1.0f / D_);
    const float var  = q * (1.0f / D_) - mean * mean;
    const float rstd = rsqrtf(var + 1e-5f);

    const float4 gm = *(const float4*)(gamma + tid * 4);
    const float4 bt = *(const float4*)(beta  + tid * 4);
    float4 o;
    o.x = (v0 - mean) * rstd * gm.x + bt.x;
    o.y = (v1 - mean) * rstd * gm.y + bt.y;
    o.z = (v2 - mean) * rstd * gm.z + bt.z;
    o.w = (v3 - mean) * rstd * gm.w + bt.w;
    *(float4*)(O + base) = o;
    if (WR) {
        __half2 h0 = __floats2half2_rn(o.x, o.y);
        __half2 h1 = __floats2half2_rn(o.z, o.w);
        uint2 u; u.x = *(uint32_t*)&h0; u.y = *(uint32_t*)&h1;
        *(uint2*)(OH + base) = u;
    }
}

// ---------------- launch ----------------
extern "C" void kernel_launch(void* const* d_in, const int* in_sizes, int n_in,
                              void* d_out, int out_size) {
    const float* h   = (const float*)d_in[0];
    const float* msk = (const float*)d_in[1];
    const float* w1  = (const float*)d_in[2];
    const float* b1  = (const float*)d_in[3];
    const float* w2  = (const float*)d_in[4];
    const float* b2  = (const float*)d_in[5];
    const float* g1  = (const float*)d_in[6];
    const float* be1 = (const float*)d_in[7];
    const float* g2  = (const float*)d_in[8];
    const float* be2 = (const float*)d_in[9];
    float* out = (float*)d_out;

    float *scores, *attn, *x, *f;
    __half *probsh, *xh, *y, *hh, *hhT, *w1t, *w2t;
    cudaGetSymbolAddress((void**)&scores, g_scores);
    cudaGetSymbolAddress((void**)&probsh, g_probsh);
    cudaGetSymbolAddress((void**)&attn,   g_attn);
    cudaGetSymbolAddress((void**)&x,      g_x);
    cudaGetSymbolAddress((void**)&xh,     g_xh);
    cudaGetSymbolAddress((void**)&y,      g_y);
    cudaGetSymbolAddress((void**)&f,      g_f);
    cudaGetSymbolAddress((void**)&hh,     g_hh);
    cudaGetSymbolAddress((void**)&hhT,    g_hhT);
    cudaGetSymbolAddress((void**)&w1t,    g_w1t);
    cudaGetSymbolAddress((void**)&w2t,    g_w2t);

    cudaFuncSetAttribute(hf_gemm<0>, cudaFuncAttributeMaxDynamicSharedMemorySize, SMEM_BYTES);
    cudaFuncSetAttribute(hf_gemm<1>, cudaFuncAttributeMaxDynamicSharedMemorySize, SMEM_BYTES);
    cudaFuncSetAttribute(hf_gemm<2>, cudaFuncAttributeMaxDynamicSharedMemorySize, SMEM_BYTES);

    // 0) fp16 conversions: h, h^T, w1^T, w2^T
    cvtH_kernel<<<(B_ * S_ * D_ / 8 + 255) / 256, 256>>>(h, hh, B_ * S_ * D_ / 8);
    cvtHT_kernel<<<dim3(D_ / 32, S_ / 32, B_), dim3(32, 8)>>>(h,  hhT, S_, D_);  // [S,D]->[D,S]
    cvtHT_kernel<<<dim3(F_ / 32, D_ / 32, 1), dim3(32, 8)>>>(w1, w1t, D_, F_);   // [D,F]->[F,D]
    cvtHT_kernel<<<dim3(D_ / 32, F_ / 32, 1), dim3(32, 8)>>>(w2, w2t, F_, D_);   // [F,D]->[D,F]

    // 1) scores = (h @ h^T) / sqrt(D)
    hf_gemm<0><<<dim3(S_ / 128, S_ / 128, B_), 256, SMEM_BYTES>>>(
        hh, hh, scores, S_, S_, D_,
        (size_t)S_ * D_, (size_t)S_ * D_, (size_t)S_ * S_, nullptr, 0.03125f);

    // 2) probs(fp16) = softmax(scores + mask)
    softmax_kernel<<<B_ * S_, 256>>>(scores, probsh, msk);

    // 3) attn = probs @ h
    hf_gemm<0><<<dim3(D_ / 128, S_ / 128, B_), 256, SMEM_BYTES>>>(
        probsh, hhT, attn, S_, D_, S_,
        (size_t)S_ * S_, (size_t)D_ * S_, (size_t)S_ * D_, nullptr, 1.0f);

    // 4) x = LN1(h + attn)  (+ fp16 copy)
    add_ln_kernel<true><<<B_ * S_, 256>>>(h, attn, g1, be1, x, xh);

    // 5) y(fp16) = gelu(x @ w1 + b1)
    hf_gemm<1><<<dim3(F_ / 128, (B_ * S_) / 128, 1), 256, SMEM_BYTES>>>(
        xh, w1t, y, B_ * S_, F_, D_, 0, 0, 0, b1, 1.0f);

    // 6) f = y @ w2 + b2
    hf_gemm<2><<<dim3(D_ / 128, (B_ * S_) / 128, 1), 256, SMEM_BYTES>>>(
        y, w2t, f, B_ * S_, D_, F_, 0, 0, 0, b2, 1.0f);

    // 7) out = LN2(x + f)
    add_ln_kernel<false><<<B_ * S_, 256>>>(x, f, g2, be2, out, nullptr);
}

// round 12
// speedup vs baseline: 2.4250x; 1.0604x over previous
#include <cuda_runtime.h>
#include <cuda_fp16.h>
#include <math.h>
#include <stdint.h>

#define B_ 4
#define S_ 2048
#define D_ 1024
#define F_ 4096

// ---------------- scratch (device globals: allocation-free) ----------------
__device__ __half g_scoresh[(size_t)B_ * S_ * S_];     //  32 MB fp16 raw scores (no mask)
__device__ __half g_probsh [(size_t)B_ * S_ * S_];     //  32 MB fp16 probs
__device__ float  g_attn  [(size_t)B_ * S_ * D_];      //  32 MB
__device__ float  g_x     [(size_t)B_ * S_ * D_];      //  32 MB exact LN1 out
__device__ __half g_xh    [(size_t)B_ * S_ * D_];      //  16 MB fp16 LN1 out
__device__ __half g_y     [(size_t)B_ * S_ * F_];      //  64 MB fp16 gelu out
__device__ float  g_f     [(size_t)B_ * S_ * D_];      //  32 MB
__device__ __half g_hh    [(size_t)B_ * S_ * D_];      //  16 MB fp16 h   [B,S,D]
__device__ __half g_hhT   [(size_t)B_ * D_ * S_];      //  16 MB fp16 h^T [B,D,S]
__device__ __half g_w1t   [(size_t)F_ * D_];           //   8 MB fp16 w1^T [F,D]
__device__ __half g_w2t   [(size_t)D_ * F_];           //   8 MB fp16 w2^T [D,F]

// ---------------- helpers ----------------
__device__ __forceinline__ float gelu_exact(float x) {
    return 0.5f * x * (1.0f + erff(x * 0.7071067811865476f));
}
__device__ __forceinline__ float warpSum(float v) {
#pragma unroll
    for (int o = 16; o; o >>= 1) v += __shfl_xor_sync(0xffffffffu, v, o);
    return v;
}
__device__ __forceinline__ float warpMax(float v) {
#pragma unroll
    for (int o = 16; o; o >>= 1) v = fmaxf(v, __shfl_xor_sync(0xffffffffu, v, o));
    return v;
}
__device__ __forceinline__ void mma16f(float* c, const uint32_t* a, uint32_t b0, uint32_t b1) {
    asm volatile(
        "mma.sync.aligned.m16n8k16.row.col.f32.f16.f16.f32 "
        "{%0,%1,%2,%3}, {%4,%5,%6,%7}, {%8,%9}, {%0,%1,%2,%3};"
        : "+f"(c[0]), "+f"(c[1]), "+f"(c[2]), "+f"(c[3])
        : "r"(a[0]), "r"(a[1]), "r"(a[2]), "r"(a[3]), "r"(b0), "r"(b1));
}
__device__ __forceinline__ void ldsm4(uint32_t& r0, uint32_t& r1, uint32_t& r2, uint32_t& r3,
                                      uint32_t addr) {
    asm volatile("ldmatrix.sync.aligned.m8n8.x4.shared.b16 {%0,%1,%2,%3}, [%4];"
                 : "=r"(r0), "=r"(r1), "=r"(r2), "=r"(r3) : "r"(addr));
}
__device__ __forceinline__ void cpasync16(uint32_t s, const void* g) {
    asm volatile("cp.async.cg.shared.global [%0], [%1], 16;" :: "r"(s), "l"(g));
}
__device__ __forceinline__ void cp_commit() { asm volatile("cp.async.commit_group;"); }
template <int N>
__device__ __forceinline__ void cp_wait() {
    asm volatile("cp.async.wait_group %0;" :: "n"(N));
}

// ---------------- f32 -> fp16 transpose convert (+ optional direct copy) -------
// src[z][R][C] -> dstT[z][C][R]; if dstN != null also dstN[z][R][C] (fp16)
__global__ void cvtHT_kernel(const float* __restrict__ src, __half* __restrict__ dstT,
                             __half* __restrict__ dstN, int R, int C) {
    __shared__ float t[32][33];
    src  += (size_t)blockIdx.z * R * C;
    dstT += (size_t)blockIdx.z * R * C;
    if (dstN) dstN += (size_t)blockIdx.z * R * C;
    const int r0 = blockIdx.y * 32, c0 = blockIdx.x * 32;
    const int tx = threadIdx.x, ty = threadIdx.y;   // 32 x 8
#pragma unroll
    for (int i = 0; i < 32; i += 8) {
        const float v = src[(size_t)(r0 + ty + i) * C + c0 + tx];
        t[ty + i][tx] = v;
        if (dstN) dstN[(size_t)(r0 + ty + i) * C + c0 + tx] = __float2half(v);
    }
    __syncthreads();
#pragma unroll
    for (int i = 0; i < 32; i += 8)
        dstT[(size_t)(c0 + ty + i) * R + r0 + tx] = __float2half(t[tx][ty + i]);
}

#define STAGE_B 16384                       // 128 rows x 128 B
#define SMEM_BYTES (3 * 2 * STAGE_B)        // 98304 B

// ---------------- FP16 mma.sync GEMM (m16n8k16), K-chunk 64 ----------------
// C[M,N] = epi( A[M,K] @ B[N,K]^T ), A,B fp16 K-major, K%64==0.
// EPI: 0 -> fp32 C = acc*alpha ; 1 -> fp16 C = gelu(acc+bias) ; 2 -> fp32 C = acc+bias
template <int EPI>
__global__ void __launch_bounds__(256, 2)
hf_gemm(const __half* __restrict__ A, const __half* __restrict__ B,
        void* __restrict__ Cv, int M, int N, int K,
        size_t sA, size_t sB, size_t sC,
        const float* __restrict__ bias, float alpha) {
    extern __shared__ float sm[];
    const uint32_t sb = (uint32_t)__cvta_generic_to_shared(sm);

    A += (size_t)blockIdx.z * sA;
    B += (size_t)blockIdx.z * sB;

    const int tid  = threadIdx.x;
    const int lane = tid & 31, warp = tid >> 5;
    const int wm = warp >> 2, wn = warp & 3;

    const int arow = tid >> 1;
    const int ac4  = (tid & 1) * 4;
    const __half* Ag = A + (size_t)(blockIdx.y * 128 + arow) * K + (tid & 1) * 32;
    const __half* Bg = B + (size_t)(blockIdx.x * 128 + arow) * K + (tid & 1) * 32;
    const uint32_t aRow = sb + (uint32_t)arow * 128;
    const uint32_t bRow = sb + 3 * STAGE_B + (uint32_t)arow * 128;
    const int rsw = arow & 7;

    auto issue = [&](int ch, int s) {
        const __half* ag = Ag + ch * 64;
        const __half* bg = Bg + ch * 64;
        const uint32_t as = aRow + s * STAGE_B;
        const uint32_t bs = bRow + s * STAGE_B;
#pragma unroll
        for (int j = 0; j < 4; j++) {
            const uint32_t off = (uint32_t)(((ac4 + j) ^ rsw) * 16);
            cpasync16(as + off, ag + j * 8);
            cpasync16(bs + off, bg + j * 8);
        }
    };

    const int lm = lane >> 3, ri = lane & 7;
    uint32_t aOff[4]; int aSel[4];
#pragma unroll
    for (int mt = 0; mt < 4; mt++) {
        const int r = wm * 64 + mt * 16 + (lm & 1) * 8 + ri;
        aOff[mt] = (uint32_t)r * 128;
        aSel[mt] = r & 7;
    }
    const int aCh = lm >> 1;
    uint32_t bOff[2]; int bSel[2];
#pragma unroll
    for (int np = 0; np < 2; np++) {
        const int r = wn * 32 + np * 16 + (lm >> 1) * 8 + ri;
        bOff[np] = (uint32_t)r * 128;
        bSel[np] = r & 7;
    }
    const int bCh = lm & 1;

    const int nch = K >> 6;

    issue(0, 0); cp_commit();
    issue(1, 1); cp_commit();

    float acc[4][4][4];
#pragma unroll
    for (int i = 0; i < 4; i++)
#pragma unroll
        for (int j = 0; j < 4; j++)
#pragma unroll
            for (int p = 0; p < 4; p++) acc[i][j][p] = 0.f;

    for (int ch = 0; ch < nch; ch++) {
        const int s = ch % 3;
        cp_wait<1>();
        __syncthreads();

        if (ch + 2 < nch) issue(ch + 2, (ch + 2) % 3);
        cp_commit();

        const uint32_t aSt = sb + s * STAGE_B;
        const uint32_t bSt = sb + 3 * STAGE_B + s * STAGE_B;

#pragma unroll
        for (int ks = 0; ks < 4; ks++) {
            uint32_t a[4][4];
#pragma unroll
            for (int mt = 0; mt < 4; mt++)
                ldsm4(a[mt][0], a[mt][1], a[mt][2], a[mt][3],
                      aSt + aOff[mt] + (uint32_t)(((2 * ks + aCh) ^ aSel[mt]) << 4));
            uint32_t bb[2][4];
#pragma unroll
            for (int np = 0; np < 2; np++)
                ldsm4(bb[np][0], bb[np][1], bb[np][2], bb[np][3],
                      bSt + bOff[np] + (uint32_t)(((2 * ks + bCh) ^ bSel[np]) << 4));
#pragma unroll
            for (int nt = 0; nt < 4; nt++) {
                const uint32_t b0 = bb[nt >> 1][(nt & 1) * 2];
                const uint32_t b1 = bb[nt >> 1][(nt & 1) * 2 + 1];
#pragma unroll
                for (int mt = 0; mt < 4; mt++) mma16f(acc[mt][nt], a[mt], b0, b1);
            }
        }
    }

    const int g = lane >> 2, tig = lane & 3;
#pragma unroll
    for (int mt = 0; mt < 4; mt++) {
        const int r0 = blockIdx.y * 128 + wm * 64 + mt * 16 + g;
#pragma unroll
        for (int nt = 0; nt < 4; nt++) {
            const int c0 = blockIdx.x * 128 + wn * 32 + nt * 8 + 2 * tig;
            float v0 = acc[mt][nt][0], v1 = acc[mt][nt][1];
            float v2 = acc[mt][nt][2], v3 = acc[mt][nt][3];
            if (EPI == 0) {
                float* C = (float*)Cv + (size_t)blockIdx.z * sC;
                v0 *= alpha; v1 *= alpha; v2 *= alpha; v3 *= alpha;
                *(float2*)(C + (size_t)r0 * N + c0)       = make_float2(v0, v1);
                *(float2*)(C + (size_t)(r0 + 8) * N + c0) = make_float2(v2, v3);
            } else {
                const float bb0 = bias[c0], bb1 = bias[c0 + 1];
                v0 += bb0; v1 += bb1; v2 += bb0; v3 += bb1;
                if (EPI == 1) {
                    __half* C = (__half*)Cv + (size_t)blockIdx.z * sC;
                    v0 = gelu_exact(v0); v1 = gelu_exact(v1);
                    v2 = gelu_exact(v2); v3 = gelu_exact(v3);
                    *(__half2*)(C + (size_t)r0 * N + c0)       = __floats2half2_rn(v0, v1);
                    *(__half2*)(C + (size_t)(r0 + 8) * N + c0) = __floats2half2_rn(v2, v3);
                } else {
                    float* C = (float*)Cv + (size_t)blockIdx.z * sC;
                    *(float2*)(C + (size_t)r0 * N + c0)       = make_float2(v0, v1);
                    *(float2*)(C + (size_t)(r0 + 8) * N + c0) = make_float2(v2, v3);
                }
            }
        }
    }
}

// ---------------- symmetric QK^T: scores = alpha * (h @ h^T), fp16 out ---------
// Only upper-triangular 128x128 blocks computed (bi <= bj); off-diagonal blocks
// are written twice: direct from registers + transposed via padded smem staging.
#define ST_STRIDE 130   // halves per staged row (65 words: column reads <=2-way)

__global__ void __launch_bounds__(256, 2)
hf_gemm_sym(const __half* __restrict__ Hm, __half* __restrict__ Ch,
            int Sn, int K, float alpha) {
    extern __shared__ float sm[];
    const uint32_t sb = (uint32_t)__cvta_generic_to_shared(sm);

    // decode upper-triangular block pair (bi <= bj)
    int t = blockIdx.x, bi = 0, rem = Sn / 128;
    while (t >= rem) { t -= rem; bi++; rem--; }
    const int bj = bi + t;

    const __half* A = Hm + (size_t)blockIdx.z * Sn * K;
    const __half* B = A;
    __half* C = Ch + (size_t)blockIdx.z * Sn * Sn;

    const int tid  = threadIdx.x;
    const int lane = tid & 31, warp = tid >> 5;
    const int wm = warp >> 2, wn = warp & 3;

    const int arow = tid >> 1;
    const int ac4  = (tid & 1) * 4;
    const __half* Ag = A + (size_t)(bi * 128 + arow) * K + (tid & 1) * 32;
    const __half* Bg = B + (size_t)(bj * 128 + arow) * K + (tid & 1) * 32;
    const uint32_t aRow = sb + (uint32_t)arow * 128;
    const uint32_t bRow = sb + 3 * STAGE_B + (uint32_t)arow * 128;
    const int rsw = arow & 7;

    auto issue = [&](int ch, int s) {
        const __half* ag = Ag + ch * 64;
        const __half* bg = Bg + ch * 64;
        const uint32_t as = aRow + s * STAGE_B;
        const uint32_t bs = bRow + s * STAGE_B;
#pragma unroll
        for (int j = 0; j < 4; j++) {
            const uint32_t off = (uint32_t)(((ac4 + j) ^ rsw) * 16);
            cpasync16(as + off, ag + j * 8);
            cpasync16(bs + off, bg + j * 8);
        }
    };

    const int lm = lane >> 3, ri = lane & 7;
    uint32_t aOff[4]; int aSel[4];
#pragma unroll
    for (int mt = 0; mt < 4; mt++) {
        const int r = wm * 64 + mt * 16 + (lm & 1) * 8 + ri;
        aOff[mt] = (uint32_t)r * 128;
        aSel[mt] = r & 7;
    }
    const int aCh = lm >> 1;
    uint32_t bOff[2]; int bSel[2];
#pragma unroll
    for (int np = 0; np < 2; np++) {
        const int r = wn * 32 + np * 16 + (lm >> 1) * 8 + ri;
        bOff[np] = (uint32_t)r * 128;
        bSel[np] = r & 7;
    }
    const int bCh = lm & 1;

    const int nch = K >> 6;

    issue(0, 0); cp_commit();
    issue(1, 1); cp_commit();

    float acc[4][4][4];
#pragma unroll
    for (int i = 0; i < 4; i++)
#pragma unroll
        for (int j = 0; j < 4; j++)
#pragma unroll
            for (int p = 0; p < 4; p++) acc[i][j][p] = 0.f;

    for (int ch = 0; ch < nch; ch++) {
        const int s = ch % 3;
        cp_wait<1>();
        __syncthreads();

        if (ch + 2 < nch) issue(ch + 2, (ch + 2) % 3);
        cp_commit();

        const uint32_t aSt = sb + s * STAGE_B;
        const uint32_t bSt = sb + 3 * STAGE_B + s * STAGE_B;

#pragma unroll
        for (int ks = 0; ks < 4; ks++) {
            uint32_t a[4][4];
#pragma unroll
            for (int mt = 0; mt < 4; mt++)
                ldsm4(a[mt][0], a[mt][1], a[mt][2], a[mt][3],
                      aSt + aOff[mt] + (uint32_t)(((2 * ks + aCh) ^ aSel[mt]) << 4));
            uint32_t bb[2][4];
#pragma unroll
            for (int np = 0; np < 2; np++)
                ldsm4(bb[np][0], bb[np][1], bb[np][2], bb[np][3],
                      bSt + bOff[np] + (uint32_t)(((2 * ks + bCh) ^ bSel[np]) << 4));
#pragma unroll
            for (int nt = 0; nt < 4; nt++) {
                const uint32_t b0 = bb[nt >> 1][(nt & 1) * 2];
                const uint32_t b1 = bb[nt >> 1][(nt & 1) * 2 + 1];
#pragma unroll
                for (int mt = 0; mt < 4; mt++) mma16f(acc[mt][nt], a[mt], b0, b1);
            }
        }
    }

    // ---- epilogue: direct block + (off-diag) transposed block via smem ----
    __syncthreads();                      // all warps done with stage smem
    __half* st = (__half*)sm;             // staging tile [128][ST_STRIDE]
    const int g = lane >> 2, tig = lane & 3;
#pragma unroll
    for (int mt = 0; mt < 4; mt++) {
        const int lr = wm * 64 + mt * 16 + g;
        const int r0 = bi * 128 + lr;
#pragma unroll
        for (int nt = 0; nt < 4; nt++) {
            const int lc = wn * 32 + nt * 8 + 2 * tig;
            const int c0 = bj * 128 + lc;
            const __half2 h01 = __floats2half2_rn(acc[mt][nt][0] * alpha, acc[mt][nt][1] * alpha);
            const __half2 h23 = __floats2half2_rn(acc[mt][nt][2] * alpha, acc[mt][nt][3] * alpha);
            *(__half2*)(C + (size_t)r0 * Sn + c0)       = h01;
            *(__half2*)(C + (size_t)(r0 + 8) * Sn + c0) = h23;
            *(__half2*)(st + lr * ST_STRIDE + lc)       = h01;
            *(__half2*)(st + (lr + 8) * ST_STRIDE + lc) = h23;
        }
    }

    if (bi != bj) {
        __syncthreads();
        // transposed block at rows bj*128 + c, cols bi*128 + r
#pragma unroll
        for (int ci = 0; ci < 16; ci++) {
            const int c = warp * 16 + ci;
            __half* outp = C + (size_t)(bj * 128 + c) * Sn + bi * 128;
            const __half2 p0 = __halves2half2(st[(2 * lane) * ST_STRIDE + c],
                                              st[(2 * lane + 1) * ST_STRIDE + c]);
            const __half2 p1 = __halves2half2(st[(64 + 2 * lane) * ST_STRIDE + c],
                                              st[(64 + 2 * lane + 1) * ST_STRIDE + c]);
            *(__half2*)(outp + 2 * lane)      = p0;
            *(__half2*)(outp + 64 + 2 * lane) = p1;
        }
    }
}

// ---------------- softmax: fp16 scores + fp32 mask -> fp16 probs ----------------
__global__ void softmax_kernel(const __half* __restrict__ P, __half* __restrict__ Ph,
                               const float* __restrict__ mask) {
    __shared__ float sh[8];
    const int row = blockIdx.x;
    const int b   = row >> 11;
    const __half* p = P + (size_t)row * S_;
    __half* ph = Ph + (size_t)row * S_;
    const float* m = mask + (size_t)b * S_;
    const int tid = threadIdx.x;          // 256 threads, 8 contiguous halves each

    const uint4 raw = ((const uint4*)p)[tid];
    const __half2* hp = (const __half2*)&raw;
    const float4 m0 = ((const float4*)m)[2 * tid];
    const float4 m1 = ((const float4*)m)[2 * tid + 1];
    float v[8];
    {
        float2 t0 = __half22float2(hp[0]), t1 = __half22float2(hp[1]);
        float2 t2 = __half22float2(hp[2]), t3 = __half22float2(hp[3]);
        v[0] = t0.x + m0.x; v[1] = t0.y + m0.y; v[2] = t1.x + m0.z; v[3] = t1.y + m0.w;
        v[4] = t2.x + m1.x; v[5] = t2.y + m1.y; v[6] = t3.x + m1.z; v[7] = t3.y + m1.w;
    }

    float mx = v[0];
#pragma unroll
    for (int i = 1; i < 8; i++) mx = fmaxf(mx, v[i]);
    mx = warpMax(mx);
    if ((tid & 31) == 0) sh[tid >> 5] = mx;
    __syncthreads();
    mx = sh[0];
#pragma unroll
    for (int j = 1; j < 8; j++) mx = fmaxf(mx, sh[j]);

    float s = 0.f;
#pragma unroll
    for (int i = 0; i < 8; i++) { v[i] = expf(v[i] - mx); s += v[i]; }
    s = warpSum(s);
    __syncthreads();
    if ((tid & 31) == 0) sh[tid >> 5] = s;
    __syncthreads();
    s = 0.f;
#pragma unroll
    for (int j = 0; j < 8; j++) s += sh[j];
    const float inv = 1.0f / s;

    uint4 o;
    __half2* op = (__half2*)&o;
    op[0] = __floats2half2_rn(v[0] * inv, v[1] * inv);
    op[1] = __floats2half2_rn(v[2] * inv, v[3] * inv);
    op[2] = __floats2half2_rn(v[4] * inv, v[5] * inv);
    op[3] = __floats2half2_rn(v[6] * inv, v[7] * inv);
    ((uint4*)ph)[tid] = o;
}

// ---------------- out = LayerNorm(X + Y); optionally also fp16 copy ----
template <bool WR>
__global__ void add_ln_kernel(const float* __restrict__ X, const float* __restrict__ Y,
                              const float* __restrict__ gamma, const float* __restrict__ beta,
                              float* __restrict__ O, __half* __restrict__ OH) {
    __shared__ float shs[8], shq[8];
    const int row = blockIdx.x;
    const int tid = threadIdx.x;
    const size_t base = (size_t)row * D_ + tid * 4;

    const float4 a = *(const float4*)(X + base);
    const float4 b = *(const float4*)(Y + base);
    const float v0 = a.x + b.x, v1 = a.y + b.y, v2 = a.z + b.z, v3 = a.w + b.w;

    float s = v0 + v1 + v2 + v3;
    float q = v0 * v0 + v1 * v1 + v2 * v2 + v3 * v3;
    s = warpSum(s); q = warpSum(q);
    if ((tid & 31) == 0) { shs[tid >> 5] = s; shq[tid >> 5] = q; }
    __syncthreads();
    s = 0.f; q = 0.f;
#pragma unroll
    for (int j = 0; j < 8; j++) { s += shs[j]; q += shq[j]; }
    const float mean = s * (1.0f / D_);
    const float var  = q * (1.0f / D_) - mean * mean;
    const float rstd = rsqrtf(var + 1e-5f);

    const float4 gm = *(const float4*)(gamma + tid * 4);
    const float4 bt = *(const float4*)(beta  + tid * 4);
    float4 o;
    o.x = (v0 - mean) * rstd * gm.x + bt.x;
    o.y = (v1 - mean) * rstd * gm.y + bt.y;
    o.z = (v2 - mean) * rstd * gm.z + bt.z;
    o.w = (v3 - mean) * rstd * gm.w + bt.w;
    *(float4*)(O + base) = o;
    if (WR) {
        __half2 h0 = __floats2half2_rn(o.x, o.y);
        __half2 h1 = __floats2half2_rn(o.z, o.w);
        uint2 u; u.x = *(uint32_t*)&h0; u.y = *(uint32_t*)&h1;
        *(uint2*)(OH + base) = u;
    }
}

// ---------------- launch ----------------
extern "C" void kernel_launch(void* const* d_in, const int* in_sizes, int n_in,
                              void* d_out, int out_size) {
    const float* h   = (const float*)d_in[0];
    const float* msk = (const float*)d_in[1];
    const float* w1  = (const float*)d_in[2];
    const float* b1  = (const float*)d_in[3];
    const float* w2  = (const float*)d_in[4];
    const float* b2  = (const float*)d_in[5];
    const float* g1  = (const float*)d_in[6];
    const float* be1 = (const float*)d_in[7];
    const float* g2  = (const float*)d_in[8];
    const float* be2 = (const float*)d_in[9];
    float* out = (float*)d_out;

    float *attn, *x, *f;
    __half *scoresh, *probsh, *xh, *y, *hh, *hhT, *w1t, *w2t;
    cudaGetSymbolAddress((void**)&scoresh, g_scoresh);
    cudaGetSymbolAddress((void**)&probsh,  g_probsh);
    cudaGetSymbolAddress((void**)&attn,    g_attn);
    cudaGetSymbolAddress((void**)&x,       g_x);
    cudaGetSymbolAddress((void**)&xh,      g_xh);
    cudaGetSymbolAddress((void**)&y,       g_y);
    cudaGetSymbolAddress((void**)&f,       g_f);
    cudaGetSymbolAddress((void**)&hh,      g_hh);
    cudaGetSymbolAddress((void**)&hhT,     g_hhT);
    cudaGetSymbolAddress((void**)&w1t,     g_w1t);
    cudaGetSymbolAddress((void**)&w2t,     g_w2t);

    cudaFuncSetAttribute(hf_gemm<0>,  cudaFuncAttributeMaxDynamicSharedMemorySize, SMEM_BYTES);
    cudaFuncSetAttribute(hf_gemm<1>,  cudaFuncAttributeMaxDynamicSharedMemorySize, SMEM_BYTES);
    cudaFuncSetAttribute(hf_gemm<2>,  cudaFuncAttributeMaxDynamicSharedMemorySize, SMEM_BYTES);
    cudaFuncSetAttribute(hf_gemm_sym, cudaFuncAttributeMaxDynamicSharedMemorySize, SMEM_BYTES);

    // 0) fp16 conversions: h -> (hh, hhT) in one pass; w1^T, w2^T
    cvtHT_kernel<<<dim3(D_ / 32, S_ / 32, B_), dim3(32, 8)>>>(h,  hhT, hh, S_, D_);
    cvtHT_kernel<<<dim3(F_ / 32, D_ / 32, 1), dim3(32, 8)>>>(w1, w1t, nullptr, D_, F_);
    cvtHT_kernel<<<dim3(D_ / 32, F_ / 32, 1), dim3(32, 8)>>>(w2, w2t, nullptr, F_, D_);

    // 1) scores(fp16) = (h @ h^T)/sqrt(D) — symmetric: 136 upper-tri blocks
    const int ntri = (S_ / 128) * (S_ / 128 + 1) / 2;   // 136
    hf_gemm_sym<<<dim3(ntri, 1, B_), 256, SMEM_BYTES>>>(hh, scoresh, S_, D_, 0.03125f);

    // 2) probs(fp16) = softmax(scores + mask)
    softmax_kernel<<<B_ * S_, 256>>>(scoresh, probsh, msk);

    // 3) attn = probs @ h
    hf_gemm<0><<<dim3(D_ / 128, S_ / 128, B_), 256, SMEM_BYTES>>>(
        probsh, hhT, attn, S_, D_, S_,
        (size_t)S_ * S_, (size_t)D_ * S_, (size_t)S_ * D_, nullptr, 1.0f);

    // 4) x = LN1(h + attn)  (+ fp16 copy)
    add_ln_kernel<true><<<B_ * S_, 256>>>(h, attn, g1, be1, x, xh);

    // 5) y(fp16) = gelu(x @ w1 + b1)
    hf_gemm<1><<<dim3(F_ / 128, (B_ * S_) / 128, 1), 256, SMEM_BYTES>>>(
        xh, w1t, y, B_ * S_, F_, D_, 0, 0, 0, b1, 1.0f);

    // 6) f = y @ w2 + b2
    hf_gemm<2><<<dim3(D_ / 128, (B_ * S_) / 128, 1), 256, SMEM_BYTES>>>(
        y, w2t, f, B_ * S_, D_, F_, 0, 0, 0, b2, 1.0f);

    // 7) out = LN2(x + f)
    add_ln_kernel<false><<<B_ * S_, 256>>>(x, f, g2, be2, out, nullptr);
}